// round 6
// baseline (speedup 1.0000x reference)
#include <cuda_runtime.h>
#include <cuda_bf16.h>
#include <cstdint>

#define EDIM   512
#define MROWS  8192
#define NCHUNK 16
#define CHUNKS 128

// ---------------- scratch (no allocation allowed) ----------------
__device__ float g_q[MROWS * EDIM];
__device__ float g_k[MROWS * EDIM];
__device__ float g_v[MROWS * EDIM];
__device__ float g_part[32 * NCHUNK * 4224];
__device__ float g_M[32 * 4096];
__device__ float g_ksum[32 * 64];
__device__ float g_vsum[32 * 64];
// bf16 hi/lo operands
__device__ __nv_bfloat16 g_xh[MROWS * EDIM];
__device__ __nv_bfloat16 g_xl[MROWS * EDIM];
__device__ __nv_bfloat16 g_wh[4 * EDIM * EDIM];
__device__ __nv_bfloat16 g_wl[4 * EDIM * EDIM];
__device__ __nv_bfloat16 g_ah[MROWS * EDIM];
__device__ __nv_bfloat16 g_al[MROWS * EDIM];
__device__ float g_bp[4 * EDIM];

// =================== helpers ===================
__device__ __forceinline__ uint32_t smem_u32(const void* p) {
    uint32_t a;
    asm("{ .reg .u64 t; cvta.to.shared.u64 t, %1; cvt.u32.u64 %0, t; }" : "=r"(a) : "l"(p));
    return a;
}
__device__ __forceinline__ uint32_t sw128(uint32_t off) { return off ^ ((off >> 3) & 0x70); }

__device__ __forceinline__ void split2(float a, float b, uint32_t& hi, uint32_t& lo) {
    __nv_bfloat16 ha = __float2bfloat16_rn(a), hb = __float2bfloat16_rn(b);
    float ra = a - __bfloat162float(ha);
    float rb = b - __bfloat162float(hb);
    __nv_bfloat16 la = __float2bfloat16_rn(ra), lb = __float2bfloat16_rn(rb);
    hi = (uint32_t)__bfloat16_as_ushort(ha) | ((uint32_t)__bfloat16_as_ushort(hb) << 16);
    lo = (uint32_t)__bfloat16_as_ushort(la) | ((uint32_t)__bfloat16_as_ushort(lb) << 16);
}
#define LDSM4(r, addr) \
    asm volatile("ldmatrix.sync.aligned.m8n8.x4.shared.b16 {%0,%1,%2,%3}, [%4];" \
        : "=r"((r)[0]), "=r"((r)[1]), "=r"((r)[2]), "=r"((r)[3]) : "r"(addr))
#define MMA16816(d, a, b0, b1) \
    asm volatile("mma.sync.aligned.m16n8k16.row.col.f32.bf16.bf16.f32 " \
        "{%0,%1,%2,%3},{%4,%5,%6,%7},{%8,%9},{%0,%1,%2,%3};" \
        : "+f"((d)[0]), "+f"((d)[1]), "+f"((d)[2]), "+f"((d)[3]) \
        : "r"((a)[0]), "r"((a)[1]), "r"((a)[2]), "r"((a)[3]), "r"(b0), "r"(b1))
#define CP16(saddr, gptr) \
    asm volatile("cp.async.cg.shared.global [%0], [%1], 16;" :: "r"(saddr), "l"(gptr))
#define CP_COMMIT() asm volatile("cp.async.commit_group;" ::: "memory")
#define CP_WAIT1()  asm volatile("cp.async.wait_group 1;" ::: "memory")
#define CP_WAIT0()  asm volatile("cp.async.wait_group 0;" ::: "memory")

// ------------- one fused fp32 -> bf16 hi/lo split for ALL operands -------------
#define NQ4  (MROWS * EDIM / 4)
#define NW4  (EDIM * EDIM / 4)
__global__ void split_all_kernel(const float4* __restrict__ q,
                                 const float4* __restrict__ wq, const float4* __restrict__ wk,
                                 const float4* __restrict__ wv, const float4* __restrict__ wo,
                                 const float* __restrict__ bq, const float* __restrict__ bk,
                                 const float* __restrict__ bv, const float* __restrict__ bo)
{
    const int i = blockIdx.x * blockDim.x + threadIdx.x;
    const int total = NQ4 + 4 * NW4;
    if (i < NQ4) {
        const float4 x = q[i];
        uint32_t h0, h1, l0, l1;
        split2(x.x, x.y, h0, l0); split2(x.z, x.w, h1, l1);
        ((uint2*)g_xh)[i] = make_uint2(h0, h1);
        ((uint2*)g_xl)[i] = make_uint2(l0, l1);
    } else if (i < total) {
        const int j = i - NQ4;
        const int w = j / NW4, off = j % NW4;
        const float4* src = (w == 0) ? wq : (w == 1) ? wk : (w == 2) ? wv : wo;
        const float4 x = src[off];
        uint32_t h0, h1, l0, l1;
        split2(x.x, x.y, h0, l0); split2(x.z, x.w, h1, l1);
        ((uint2*)g_wh)[j] = make_uint2(h0, h1);
        ((uint2*)g_wl)[j] = make_uint2(l0, l1);
    } else if (i < total + EDIM) {
        const int t = i - total;
        g_bp[t] = bq[t];
        g_bp[EDIM + t] = bk[t];
        g_bp[2 * EDIM + t] = bv[t];
        g_bp[3 * EDIM + t] = bo[t];
    }
}

// ======== bf16 3-pass warp-MMA GEMM, cp.async 2-stage pipeline ========
// optional fused 64-wide softmax epilogue for Q/K outputs.
#define STAGE_BYTES 65536
#define SMEM_DYN (2 * STAGE_BYTES)

extern __shared__ __align__(1024) char dynsmem[];

__global__ __launch_bounds__(256, 1)
void gemm_bf16(const __nv_bfloat16* __restrict__ Ah, const __nv_bfloat16* __restrict__ Al,
               int wbase, int do_softmax,
               float* __restrict__ out0, float* __restrict__ out1, float* __restrict__ out2)
{
    const uint32_t sbase = smem_u32(dynsmem);
    const int tid = threadIdx.x;
    const int wid = tid >> 5, lid = tid & 31;
    const int warp_m = wid >> 2;
    const int warp_n = wid & 3;
    const int nb = blockIdx.x;
    const int bm = blockIdx.y << 7;
    const int bn = (nb & 3) << 7;
    const int sel = nb >> 2;
    float* outp = (sel == 0) ? out0 : ((sel == 1) ? out1 : out2);
    const int wrow = wbase + nb * 128;
    const int fuse_sm = do_softmax && (sel < 2);

    int cp_r[4], cp_cg[4];
    uint32_t cp_soff[4];
    #pragma unroll
    for (int it = 0; it < 4; ++it) {
        const int g = tid + it * 256;
        cp_r[it] = g >> 3;
        cp_cg[it] = g & 7;
        cp_soff[it] = sw128((uint32_t)(cp_r[it] * 128 + cp_cg[it] * 16));
    }

    float acc[4][4][4] = {};
    const int a_row = warp_m * 64 + (lid & 7) + ((lid >> 3) & 1) * 8;
    const int a_kb  = (lid >> 4) * 16;
    const int b_row = warp_n * 32 + (lid & 7) + (lid >> 4) * 8;
    const int b_kb  = ((lid >> 3) & 1) * 16;

    auto issue = [&](int c, int buf) {
        const uint32_t ah = sbase + buf * STAGE_BYTES;
        const uint32_t al = ah + 16384, bh = ah + 32768, bl = ah + 49152;
        const int kof = c * 64;
        #pragma unroll
        for (int it = 0; it < 4; ++it) {
            const size_t aoff = (size_t)(bm + cp_r[it]) * EDIM + kof + cp_cg[it] * 8;
            const size_t boff = (size_t)(wrow + cp_r[it]) * EDIM + kof + cp_cg[it] * 8;
            CP16(ah + cp_soff[it], Ah + aoff);
            CP16(al + cp_soff[it], Al + aoff);
            CP16(bh + cp_soff[it], g_wh + boff);
            CP16(bl + cp_soff[it], g_wl + boff);
        }
        CP_COMMIT();
    };

    issue(0, 0);

    for (int c = 0; c < 8; ++c) {
        if (c < 7) { issue(c + 1, (c + 1) & 1); CP_WAIT1(); }
        else       { CP_WAIT0(); }
        __syncthreads();

        const uint32_t ah = sbase + (c & 1) * STAGE_BYTES;
        const uint32_t al = ah + 16384, bh = ah + 32768, bl = ah + 49152;

        #pragma unroll
        for (int ks = 0; ks < 4; ++ks) {
            uint32_t Ahf[4][4], Alf[4][4];
            #pragma unroll
            for (int mt = 0; mt < 4; ++mt) {
                const uint32_t off = sw128((uint32_t)((a_row + mt * 16) * 128 + ks * 32 + a_kb));
                LDSM4(Ahf[mt], ah + off);
                LDSM4(Alf[mt], al + off);
            }
            uint32_t Bh[8], Bl[8];
            #pragma unroll
            for (int np = 0; np < 2; ++np) {
                const uint32_t off = sw128((uint32_t)((b_row + np * 16) * 128 + ks * 32 + b_kb));
                LDSM4(&Bh[np * 4], bh + off);
                LDSM4(&Bl[np * 4], bl + off);
            }
            #pragma unroll
            for (int mt = 0; mt < 4; ++mt)
                #pragma unroll
                for (int nt = 0; nt < 4; ++nt) {
                    MMA16816(acc[mt][nt], Ahf[mt], Bh[nt * 2], Bh[nt * 2 + 1]);
                    MMA16816(acc[mt][nt], Ahf[mt], Bl[nt * 2], Bl[nt * 2 + 1]);
                    MMA16816(acc[mt][nt], Alf[mt], Bh[nt * 2], Bh[nt * 2 + 1]);
                }
        }
        __syncthreads();
    }

    if (fuse_sm) {
        // stage tile (+bias) into smem, then per-row 64-wide softmax
        float* sm = (float*)dynsmem;   // stride 130 floats
        #pragma unroll
        for (int mt = 0; mt < 4; ++mt) {
            const int r0 = warp_m * 64 + mt * 16 + (lid >> 2);
            #pragma unroll
            for (int nt = 0; nt < 4; ++nt) {
                const int cit = warp_n * 32 + nt * 8 + ((lid & 3) << 1);
                const float b0 = g_bp[wrow + cit], b1 = g_bp[wrow + cit + 1];
                sm[r0 * 130 + cit]           = acc[mt][nt][0] + b0;
                sm[r0 * 130 + cit + 1]       = acc[mt][nt][1] + b1;
                sm[(r0 + 8) * 130 + cit]     = acc[mt][nt][2] + b0;
                sm[(r0 + 8) * 130 + cit + 1] = acc[mt][nt][3] + b1;
            }
        }
        __syncthreads();
        #pragma unroll
        for (int rr = 0; rr < 16; ++rr) {
            const int r = wid * 16 + rr;
            #pragma unroll
            for (int g = 0; g < 2; ++g) {
                float a = sm[r * 130 + g * 64 + lid];
                float b = sm[r * 130 + g * 64 + lid + 32];
                float m = fmaxf(a, b);
                #pragma unroll
                for (int o = 16; o > 0; o >>= 1)
                    m = fmaxf(m, __shfl_xor_sync(0xffffffffu, m, o));
                float ea = __expf(a - m), eb = __expf(b - m);
                float s = ea + eb;
                #pragma unroll
                for (int o = 16; o > 0; o >>= 1)
                    s += __shfl_xor_sync(0xffffffffu, s, o);
                const float inv = 1.0f / s;
                float* p = outp + (size_t)(bm + r) * EDIM + bn + g * 64;
                p[lid]      = ea * inv;
                p[lid + 32] = eb * inv;
            }
        }
    } else {
        #pragma unroll
        for (int mt = 0; mt < 4; ++mt) {
            const int r0 = bm + warp_m * 64 + mt * 16 + (lid >> 2);
            #pragma unroll
            for (int nt = 0; nt < 4; ++nt) {
                const int cit = warp_n * 32 + nt * 8 + ((lid & 3) << 1);
                const float b0 = g_bp[wrow + cit], b1 = g_bp[wrow + cit + 1];
                const int col = bn + cit;
                float2 o0 = make_float2(acc[mt][nt][0] + b0, acc[mt][nt][1] + b1);
                float2 o1 = make_float2(acc[mt][nt][2] + b0, acc[mt][nt][3] + b1);
                *(float2*)(outp + (size_t)r0 * EDIM + col)       = o0;
                *(float2*)(outp + (size_t)(r0 + 8) * EDIM + col) = o1;
            }
        }
    }
}

// ---------------- per-head partial stats: M = K^T V, Ksum, Vsum -------------
__global__ __launch_bounds__(256)
void stats_partial_kernel()
{
    const int n = blockIdx.y;
    const int b = n >> 3, h = n & 7;
    const int s0 = blockIdx.x * CHUNKS;
    __shared__ float Ks[32][68];
    __shared__ float Vs[32][68];
    const int tid = threadIdx.x;
    const int tx = tid & 15, ty = tid >> 4;
    const int sl = tid >> 3;
    const int dq = (tid & 7) << 3;

    float mreg[4][4] = {};
    float sreg = 0.f;

    for (int st = 0; st < CHUNKS; st += 32) {
        const int s = s0 + st + sl;
        const size_t roff = (size_t)(s * 4 + b) * EDIM + h * 64 + dq;
        const float4 k0 = *(const float4*)(g_k + roff);
        const float4 k1 = *(const float4*)(g_k + roff + 4);
        const float4 v0 = *(const float4*)(g_v + roff);
        const float4 v1 = *(const float4*)(g_v + roff + 4);
        __syncthreads();
        *(float4*)&Ks[sl][dq]     = k0;
        *(float4*)&Ks[sl][dq + 4] = k1;
        *(float4*)&Vs[sl][dq]     = v0;
        *(float4*)&Vs[sl][dq + 4] = v1;
        __syncthreads();
        #pragma unroll
        for (int ss = 0; ss < 32; ++ss) {
            float kf[4], vf[4];
            *(float4*)kf = *(const float4*)&Ks[ss][ty * 4];
            *(float4*)vf = *(const float4*)&Vs[ss][tx * 4];
            #pragma unroll
            for (int i = 0; i < 4; ++i)
                #pragma unroll
                for (int j = 0; j < 4; ++j)
                    mreg[i][j] += kf[i] * vf[j];
        }
        if (tid < 64) {
            #pragma unroll
            for (int ss = 0; ss < 32; ++ss) sreg += Ks[ss][tid];
        } else if (tid < 128) {
            #pragma unroll
            for (int ss = 0; ss < 32; ++ss) sreg += Vs[ss][tid - 64];
        }
    }
    float* pb = g_part + (size_t)(n * NCHUNK + blockIdx.x) * 4224;
    #pragma unroll
    for (int i = 0; i < 4; ++i) {
        float4 w;
        w.x = mreg[i][0]; w.y = mreg[i][1]; w.z = mreg[i][2]; w.w = mreg[i][3];
        *(float4*)(pb + (ty * 4 + i) * 64 + tx * 4) = w;
    }
    if (tid < 128) pb[4096 + tid] = sreg;
}

__global__ void stats_reduce_kernel()
{
    const int n = blockIdx.x;
    for (int i = threadIdx.x; i < 4224; i += 256) {
        float s = 0.f;
        #pragma unroll
        for (int c = 0; c < NCHUNK; ++c)
            s += g_part[(size_t)(n * NCHUNK + c) * 4224 + i];
        if (i < 4096)       g_M[n * 4096 + i] = s;
        else if (i < 4160)  g_ksum[n * 64 + (i - 4096)] = s;
        else                g_vsum[n * 64 + (i - 4160)] = s;
    }
}

// ---- combine: a = (62*Vsum + 2*q@M) / (62*2048 + 2*q.Ksum), emit bf16 hi/lo ----
__global__ __launch_bounds__(256)
void combine_kernel()
{
    const int n = blockIdx.y;
    const int b = n >> 3, h = n & 7;
    const int l0 = blockIdx.x << 6;
    __shared__ float Ms[64][64];
    __shared__ float Qs[64][65];
    __shared__ float ksum_s[64], vsum_s[64], den_s[64];
    const int tid = threadIdx.x;

    {
        const float4* Mp = (const float4*)(g_M + (size_t)n * 4096);
        float4* Md = (float4*)&Ms[0][0];
        for (int i = tid; i < 1024; i += 256) Md[i] = Mp[i];
    }
    if (tid < 64) { ksum_s[tid] = g_ksum[n * 64 + tid]; vsum_s[tid] = g_vsum[n * 64 + tid]; }
    {
        const int l = tid >> 2;
        const int dq = (tid & 3) << 4;
        const float* qr = g_q + (size_t)((l0 + l) * 4 + b) * EDIM + h * 64 + dq;
        #pragma unroll
        for (int u = 0; u < 16; u += 4) {
            const float4 qv = *(const float4*)(qr + u);
            Qs[dq + u + 0][l] = qv.x; Qs[dq + u + 1][l] = qv.y;
            Qs[dq + u + 2][l] = qv.z; Qs[dq + u + 3][l] = qv.w;
        }
    }
    __syncthreads();
    if (tid < 64) {
        float s = 0.f;
        #pragma unroll
        for (int d = 0; d < 64; ++d) s += Qs[d][tid] * ksum_s[d];
        den_s[tid] = 1.0f / (126976.0f + 2.0f * s);
    }
    __syncthreads();
    const int tx = tid & 15, ty = tid >> 4;
    float acc[4][4] = {};
    #pragma unroll
    for (int d = 0; d < 64; ++d) {
        float qf[4], mf[4];
        #pragma unroll
        for (int i = 0; i < 4; ++i) qf[i] = Qs[d][ty * 4 + i];
        *(float4*)mf = *(const float4*)&Ms[d][tx * 4];
        #pragma unroll
        for (int i = 0; i < 4; ++i)
            #pragma unroll
            for (int j = 0; j < 4; ++j)
                acc[i][j] += qf[i] * mf[j];
    }
    #pragma unroll
    for (int i = 0; i < 4; ++i) {
        const int l = ty * 4 + i;
        const float inv = den_s[l];
        float ox = (62.f * vsum_s[tx * 4 + 0] + 2.f * acc[i][0]) * inv;
        float oy = (62.f * vsum_s[tx * 4 + 1] + 2.f * acc[i][1]) * inv;
        float oz = (62.f * vsum_s[tx * 4 + 2] + 2.f * acc[i][2]) * inv;
        float ow = (62.f * vsum_s[tx * 4 + 3] + 2.f * acc[i][3]) * inv;
        uint32_t h0, h1, lo0, lo1;
        split2(ox, oy, h0, lo0);
        split2(oz, ow, h1, lo1);
        const size_t off = (size_t)((l0 + l) * 4 + b) * EDIM + h * 64 + tx * 4;
        *(uint2*)(g_ah + off) = make_uint2(h0, h1);
        *(uint2*)(g_al + off) = make_uint2(lo0, lo1);
    }
}

// ---------------- launch -----------------------------------------------------
extern "C" void kernel_launch(void* const* d_in, const int* in_sizes, int n_in,
                              void* d_out, int out_size)
{
    const float* query = (const float*)d_in[0];
    const float* Wq = (const float*)d_in[1];
    const float* bq = (const float*)d_in[2];
    const float* Wk = (const float*)d_in[3];
    const float* bk = (const float*)d_in[4];
    const float* Wv = (const float*)d_in[5];
    const float* bv = (const float*)d_in[6];
    const float* Wo = (const float*)d_in[7];
    const float* bo = (const float*)d_in[8];
    float* out = (float*)d_out;

    float *qp, *kp, *vp;
    __nv_bfloat16 *xh, *xl, *ahp, *alp;
    cudaGetSymbolAddress((void**)&qp, g_q);
    cudaGetSymbolAddress((void**)&kp, g_k);
    cudaGetSymbolAddress((void**)&vp, g_v);
    cudaGetSymbolAddress((void**)&xh, g_xh);
    cudaGetSymbolAddress((void**)&xl, g_xl);
    cudaGetSymbolAddress((void**)&ahp, g_ah);
    cudaGetSymbolAddress((void**)&alp, g_al);

    cudaFuncSetAttribute(gemm_bf16, cudaFuncAttributeMaxDynamicSharedMemorySize, SMEM_DYN);

    const int total = NQ4 + 4 * NW4 + EDIM;
    split_all_kernel<<<(total + 255) / 256, 256>>>(
        (const float4*)query, (const float4*)Wq, (const float4*)Wk,
        (const float4*)Wv, (const float4*)Wo, bq, bk, bv, bo);

    // fused QKV GEMM with softmax epilogue on Q/K
    gemm_bf16<<<dim3(12, 64), 256, SMEM_DYN>>>(xh, xl, 0, 1, qp, kp, vp);
    stats_partial_kernel<<<dim3(NCHUNK, 32), 256>>>();
    stats_reduce_kernel<<<32, 256>>>();
    combine_kernel<<<dim3(32, 32), 256>>>();
    // O GEMM
    gemm_bf16<<<dim3(4, 64), 256, SMEM_DYN>>>(ahp, alp, 3 * EDIM, 0, out, out, out);
}

// round 7
// speedup vs baseline: 1.3542x; 1.3542x over previous
#include <cuda_runtime.h>
#include <cuda_fp16.h>
#include <cstdint>

#define EDIM   512
#define MROWS  8192
#define NCHUNK 16
#define CHUNKS 128

// ---------------- scratch (no allocation allowed) ----------------
__device__ float g_q[MROWS * EDIM];
__device__ float g_k[MROWS * EDIM];
__device__ float g_v[MROWS * EDIM];
__device__ float g_part[32 * NCHUNK * 4224];
__device__ float g_M[32 * 4096];
__device__ float g_ksum[32 * 64];
__device__ float g_vsum[32 * 64];
// fp16 operands: A single-precision-hi only, W hi+lo
__device__ __half g_xh[MROWS * EDIM];      // query fp16
__device__ __half g_wh[4 * EDIM * EDIM];   // Wq|Wk|Wv|Wo hi
__device__ __half g_wl[4 * EDIM * EDIM];   // residual lo
__device__ __half g_ah[MROWS * EDIM];      // attention-out fp16
__device__ float g_bp[4 * EDIM];

// =================== helpers ===================
__device__ __forceinline__ uint32_t smem_u32(const void* p) {
    uint32_t a;
    asm("{ .reg .u64 t; cvta.to.shared.u64 t, %1; cvt.u32.u64 %0, t; }" : "=r"(a) : "l"(p));
    return a;
}
__device__ __forceinline__ uint32_t sw128(uint32_t off) { return off ^ ((off >> 3) & 0x70); }

// pack two fp32 to fp16x2 (hi) and residual fp16x2 (lo)
__device__ __forceinline__ void split2h(float a, float b, uint32_t& hi, uint32_t& lo) {
    __half ha = __float2half_rn(a), hb = __float2half_rn(b);
    float ra = a - __half2float(ha);
    float rb = b - __half2float(hb);
    __half la = __float2half_rn(ra), lb = __float2half_rn(rb);
    hi = (uint32_t)__half_as_ushort(ha) | ((uint32_t)__half_as_ushort(hb) << 16);
    lo = (uint32_t)__half_as_ushort(la) | ((uint32_t)__half_as_ushort(lb) << 16);
}
__device__ __forceinline__ uint32_t pack2h(float a, float b) {
    __half2 h = __floats2half2_rn(a, b);
    return *(uint32_t*)&h;
}
#define LDSM4(r, addr) \
    asm volatile("ldmatrix.sync.aligned.m8n8.x4.shared.b16 {%0,%1,%2,%3}, [%4];" \
        : "=r"((r)[0]), "=r"((r)[1]), "=r"((r)[2]), "=r"((r)[3]) : "r"(addr))
#define MMA16816(d, a, b0, b1) \
    asm volatile("mma.sync.aligned.m16n8k16.row.col.f32.f16.f16.f32 " \
        "{%0,%1,%2,%3},{%4,%5,%6,%7},{%8,%9},{%0,%1,%2,%3};" \
        : "+f"((d)[0]), "+f"((d)[1]), "+f"((d)[2]), "+f"((d)[3]) \
        : "r"((a)[0]), "r"((a)[1]), "r"((a)[2]), "r"((a)[3]), "r"(b0), "r"(b1))
#define CP16(saddr, gptr) \
    asm volatile("cp.async.cg.shared.global [%0], [%1], 16;" :: "r"(saddr), "l"(gptr))
#define CP_COMMIT() asm volatile("cp.async.commit_group;" ::: "memory")
#define CP_WAIT1()  asm volatile("cp.async.wait_group 1;" ::: "memory")
#define CP_WAIT0()  asm volatile("cp.async.wait_group 0;" ::: "memory")

// ------------- one fused fp32 -> fp16 conversion for ALL operands -------------
#define NQ4  (MROWS * EDIM / 4)
#define NW4  (EDIM * EDIM / 4)
__global__ void split_all_kernel(const float4* __restrict__ q,
                                 const float4* __restrict__ wq, const float4* __restrict__ wk,
                                 const float4* __restrict__ wv, const float4* __restrict__ wo,
                                 const float* __restrict__ bq, const float* __restrict__ bk,
                                 const float* __restrict__ bv, const float* __restrict__ bo)
{
    const int i = blockIdx.x * blockDim.x + threadIdx.x;
    const int total = NQ4 + 4 * NW4;
    if (i < NQ4) {
        const float4 x = q[i];
        ((uint2*)g_xh)[i] = make_uint2(pack2h(x.x, x.y), pack2h(x.z, x.w));
    } else if (i < total) {
        const int j = i - NQ4;
        const int w = j / NW4, off = j % NW4;
        const float4* src = (w == 0) ? wq : (w == 1) ? wk : (w == 2) ? wv : wo;
        const float4 x = src[off];
        uint32_t h0, h1, l0, l1;
        split2h(x.x, x.y, h0, l0); split2h(x.z, x.w, h1, l1);
        ((uint2*)g_wh)[j] = make_uint2(h0, h1);
        ((uint2*)g_wl)[j] = make_uint2(l0, l1);
    } else if (i < total + EDIM) {
        const int t = i - total;
        g_bp[t] = bq[t];
        g_bp[EDIM + t] = bk[t];
        g_bp[2 * EDIM + t] = bv[t];
        g_bp[3 * EDIM + t] = bo[t];
    }
}

// ======== fp16 2-pass warp-MMA GEMM: C = A @ (Wh+Wl)^T + bias ========
// stage = Ah(16K) + Bh(16K) + Bl(16K) = 48KB, 2 stages -> occ 2.
#define STAGE_BYTES 49152
#define SMEM_DYN (2 * STAGE_BYTES)

extern __shared__ __align__(1024) char dynsmem[];

__global__ __launch_bounds__(256, 2)
void gemm_f16(const __half* __restrict__ Ah,
              int wbase, int do_softmax,
              float* __restrict__ out0, float* __restrict__ out1, float* __restrict__ out2)
{
    const uint32_t sbase = smem_u32(dynsmem);
    const int tid = threadIdx.x;
    const int wid = tid >> 5, lid = tid & 31;
    const int warp_m = wid >> 2;
    const int warp_n = wid & 3;
    const int nb = blockIdx.x;
    const int bm = blockIdx.y << 7;
    const int bn = (nb & 3) << 7;
    const int sel = nb >> 2;
    float* outp = (sel == 0) ? out0 : ((sel == 1) ? out1 : out2);
    const int wrow = wbase + nb * 128;
    const int fuse_sm = do_softmax && (sel < 2);

    int cp_r[4], cp_cg[4];
    uint32_t cp_soff[4];
    #pragma unroll
    for (int it = 0; it < 4; ++it) {
        const int g = tid + it * 256;
        cp_r[it] = g >> 3;
        cp_cg[it] = g & 7;
        cp_soff[it] = sw128((uint32_t)(cp_r[it] * 128 + cp_cg[it] * 16));
    }

    float acc[4][4][4] = {};
    const int a_row = warp_m * 64 + (lid & 7) + ((lid >> 3) & 1) * 8;
    const int a_kb  = (lid >> 4) * 16;
    const int b_row = warp_n * 32 + (lid & 7) + (lid >> 4) * 8;
    const int b_kb  = ((lid >> 3) & 1) * 16;

    auto issue = [&](int c, int buf) {
        const uint32_t ah = sbase + buf * STAGE_BYTES;
        const uint32_t bh = ah + 16384, bl = ah + 32768;
        const int kof = c * 64;
        #pragma unroll
        for (int it = 0; it < 4; ++it) {
            const size_t aoff = (size_t)(bm + cp_r[it]) * EDIM + kof + cp_cg[it] * 8;
            const size_t boff = (size_t)(wrow + cp_r[it]) * EDIM + kof + cp_cg[it] * 8;
            CP16(ah + cp_soff[it], Ah + aoff);
            CP16(bh + cp_soff[it], g_wh + boff);
            CP16(bl + cp_soff[it], g_wl + boff);
        }
        CP_COMMIT();
    };

    issue(0, 0);

    for (int c = 0; c < 8; ++c) {
        if (c < 7) { issue(c + 1, (c + 1) & 1); CP_WAIT1(); }
        else       { CP_WAIT0(); }
        __syncthreads();

        const uint32_t ah = sbase + (c & 1) * STAGE_BYTES;
        const uint32_t bh = ah + 16384, bl = ah + 32768;

        #pragma unroll
        for (int ks = 0; ks < 4; ++ks) {
            uint32_t Ahf[4][4];
            #pragma unroll
            for (int mt = 0; mt < 4; ++mt) {
                const uint32_t off = sw128((uint32_t)((a_row + mt * 16) * 128 + ks * 32 + a_kb));
                LDSM4(Ahf[mt], ah + off);
            }
            uint32_t Bh[8], Bl[8];
            #pragma unroll
            for (int np = 0; np < 2; ++np) {
                const uint32_t off = sw128((uint32_t)((b_row + np * 16) * 128 + ks * 32 + b_kb));
                LDSM4(&Bh[np * 4], bh + off);
                LDSM4(&Bl[np * 4], bl + off);
            }
            #pragma unroll
            for (int mt = 0; mt < 4; ++mt)
                #pragma unroll
                for (int nt = 0; nt < 4; ++nt) {
                    MMA16816(acc[mt][nt], Ahf[mt], Bh[nt * 2], Bh[nt * 2 + 1]);
                    MMA16816(acc[mt][nt], Ahf[mt], Bl[nt * 2], Bl[nt * 2 + 1]);
                }
        }
        __syncthreads();
    }

    if (fuse_sm) {
        float* sm = (float*)dynsmem;   // 128 rows x stride 130
        #pragma unroll
        for (int mt = 0; mt < 4; ++mt) {
            const int r0 = warp_m * 64 + mt * 16 + (lid >> 2);
            #pragma unroll
            for (int nt = 0; nt < 4; ++nt) {
                const int cit = warp_n * 32 + nt * 8 + ((lid & 3) << 1);
                const float b0 = g_bp[wrow + cit], b1 = g_bp[wrow + cit + 1];
                sm[r0 * 130 + cit]           = acc[mt][nt][0] + b0;
                sm[r0 * 130 + cit + 1]       = acc[mt][nt][1] + b1;
                sm[(r0 + 8) * 130 + cit]     = acc[mt][nt][2] + b0;
                sm[(r0 + 8) * 130 + cit + 1] = acc[mt][nt][3] + b1;
            }
        }
        __syncthreads();
        #pragma unroll
        for (int rr = 0; rr < 16; ++rr) {
            const int r = wid * 16 + rr;
            #pragma unroll
            for (int g = 0; g < 2; ++g) {
                float a = sm[r * 130 + g * 64 + lid];
                float b = sm[r * 130 + g * 64 + lid + 32];
                float m = fmaxf(a, b);
                #pragma unroll
                for (int o = 16; o > 0; o >>= 1)
                    m = fmaxf(m, __shfl_xor_sync(0xffffffffu, m, o));
                float ea = __expf(a - m), eb = __expf(b - m);
                float s = ea + eb;
                #pragma unroll
                for (int o = 16; o > 0; o >>= 1)
                    s += __shfl_xor_sync(0xffffffffu, s, o);
                const float inv = 1.0f / s;
                float* p = outp + (size_t)(bm + r) * EDIM + bn + g * 64;
                p[lid]      = ea * inv;
                p[lid + 32] = eb * inv;
            }
        }
    } else {
        #pragma unroll
        for (int mt = 0; mt < 4; ++mt) {
            const int r0 = bm + warp_m * 64 + mt * 16 + (lid >> 2);
            #pragma unroll
            for (int nt = 0; nt < 4; ++nt) {
                const int cit = warp_n * 32 + nt * 8 + ((lid & 3) << 1);
                const float b0 = g_bp[wrow + cit], b1 = g_bp[wrow + cit + 1];
                const int col = bn + cit;
                float2 o0 = make_float2(acc[mt][nt][0] + b0, acc[mt][nt][1] + b1);
                float2 o1 = make_float2(acc[mt][nt][2] + b0, acc[mt][nt][3] + b1);
                *(float2*)(outp + (size_t)r0 * EDIM + col)       = o0;
                *(float2*)(outp + (size_t)(r0 + 8) * EDIM + col) = o1;
            }
        }
    }
}

// ---------------- per-head partial stats: M = K^T V, Ksum, Vsum -------------
__global__ __launch_bounds__(256)
void stats_partial_kernel()
{
    const int n = blockIdx.y;
    const int b = n >> 3, h = n & 7;
    const int s0 = blockIdx.x * CHUNKS;
    __shared__ float Ks[32][68];
    __shared__ float Vs[32][68];
    const int tid = threadIdx.x;
    const int tx = tid & 15, ty = tid >> 4;
    const int sl = tid >> 3;
    const int dq = (tid & 7) << 3;

    float mreg[4][4] = {};
    float sreg = 0.f;

    for (int st = 0; st < CHUNKS; st += 32) {
        const int s = s0 + st + sl;
        const size_t roff = (size_t)(s * 4 + b) * EDIM + h * 64 + dq;
        const float4 k0 = *(const float4*)(g_k + roff);
        const float4 k1 = *(const float4*)(g_k + roff + 4);
        const float4 v0 = *(const float4*)(g_v + roff);
        const float4 v1 = *(const float4*)(g_v + roff + 4);
        __syncthreads();
        *(float4*)&Ks[sl][dq]     = k0;
        *(float4*)&Ks[sl][dq + 4] = k1;
        *(float4*)&Vs[sl][dq]     = v0;
        *(float4*)&Vs[sl][dq + 4] = v1;
        __syncthreads();
        #pragma unroll
        for (int ss = 0; ss < 32; ++ss) {
            float kf[4], vf[4];
            *(float4*)kf = *(const float4*)&Ks[ss][ty * 4];
            *(float4*)vf = *(const float4*)&Vs[ss][tx * 4];
            #pragma unroll
            for (int i = 0; i < 4; ++i)
                #pragma unroll
                for (int j = 0; j < 4; ++j)
                    mreg[i][j] += kf[i] * vf[j];
        }
        if (tid < 64) {
            #pragma unroll
            for (int ss = 0; ss < 32; ++ss) sreg += Ks[ss][tid];
        } else if (tid < 128) {
            #pragma unroll
            for (int ss = 0; ss < 32; ++ss) sreg += Vs[ss][tid - 64];
        }
    }
    float* pb = g_part + (size_t)(n * NCHUNK + blockIdx.x) * 4224;
    #pragma unroll
    for (int i = 0; i < 4; ++i) {
        float4 w;
        w.x = mreg[i][0]; w.y = mreg[i][1]; w.z = mreg[i][2]; w.w = mreg[i][3];
        *(float4*)(pb + (ty * 4 + i) * 64 + tx * 4) = w;
    }
    if (tid < 128) pb[4096 + tid] = sreg;
}

// parallel reduce: one thread per output element
__global__ void stats_reduce_kernel()
{
    const int i = blockIdx.x * 256 + threadIdx.x;
    if (i >= 32 * 4224) return;
    const int n = i / 4224, j = i % 4224;
    float s = 0.f;
    #pragma unroll
    for (int c = 0; c < NCHUNK; ++c)
        s += g_part[(size_t)(n * NCHUNK + c) * 4224 + j];
    if (j < 4096)       g_M[n * 4096 + j] = s;
    else if (j < 4160)  g_ksum[n * 64 + (j - 4096)] = s;
    else                g_vsum[n * 64 + (j - 4160)] = s;
}

// ---- combine: a = (62*Vsum + 2*q@M) / (62*2048 + 2*q.Ksum), emit fp16 ----
__global__ __launch_bounds__(256)
void combine_kernel()
{
    const int n = blockIdx.y;
    const int b = n >> 3, h = n & 7;
    const int l0 = blockIdx.x << 6;
    __shared__ float Ms[64][64];
    __shared__ float Qs[64][65];
    __shared__ float ksum_s[64], vsum_s[64], den_s[64];
    const int tid = threadIdx.x;

    {
        const float4* Mp = (const float4*)(g_M + (size_t)n * 4096);
        float4* Md = (float4*)&Ms[0][0];
        for (int i = tid; i < 1024; i += 256) Md[i] = Mp[i];
    }
    if (tid < 64) { ksum_s[tid] = g_ksum[n * 64 + tid]; vsum_s[tid] = g_vsum[n * 64 + tid]; }
    {
        const int l = tid >> 2;
        const int dq = (tid & 3) << 4;
        const float* qr = g_q + (size_t)((l0 + l) * 4 + b) * EDIM + h * 64 + dq;
        #pragma unroll
        for (int u = 0; u < 16; u += 4) {
            const float4 qv = *(const float4*)(qr + u);
            Qs[dq + u + 0][l] = qv.x; Qs[dq + u + 1][l] = qv.y;
            Qs[dq + u + 2][l] = qv.z; Qs[dq + u + 3][l] = qv.w;
        }
    }
    __syncthreads();
    if (tid < 64) {
        float s = 0.f;
        #pragma unroll
        for (int d = 0; d < 64; ++d) s += Qs[d][tid] * ksum_s[d];
        den_s[tid] = 1.0f / (126976.0f + 2.0f * s);
    }
    __syncthreads();
    const int tx = tid & 15, ty = tid >> 4;
    float acc[4][4] = {};
    #pragma unroll
    for (int d = 0; d < 64; ++d) {
        float qf[4], mf[4];
        #pragma unroll
        for (int i = 0; i < 4; ++i) qf[i] = Qs[d][ty * 4 + i];
        *(float4*)mf = *(const float4*)&Ms[d][tx * 4];
        #pragma unroll
        for (int i = 0; i < 4; ++i)
            #pragma unroll
            for (int j = 0; j < 4; ++j)
                acc[i][j] += qf[i] * mf[j];
    }
    #pragma unroll
    for (int i = 0; i < 4; ++i) {
        const int l = ty * 4 + i;
        const float inv = den_s[l];
        float ox = (62.f * vsum_s[tx * 4 + 0] + 2.f * acc[i][0]) * inv;
        float oy = (62.f * vsum_s[tx * 4 + 1] + 2.f * acc[i][1]) * inv;
        float oz = (62.f * vsum_s[tx * 4 + 2] + 2.f * acc[i][2]) * inv;
        float ow = (62.f * vsum_s[tx * 4 + 3] + 2.f * acc[i][3]) * inv;
        const size_t off = (size_t)((l0 + l) * 4 + b) * EDIM + h * 64 + tx * 4;
        *(uint2*)(g_ah + off) = make_uint2(pack2h(ox, oy), pack2h(oz, ow));
    }
}

// ---------------- launch -----------------------------------------------------
extern "C" void kernel_launch(void* const* d_in, const int* in_sizes, int n_in,
                              void* d_out, int out_size)
{
    const float* query = (const float*)d_in[0];
    const float* Wq = (const float*)d_in[1];
    const float* bq = (const float*)d_in[2];
    const float* Wk = (const float*)d_in[3];
    const float* bk = (const float*)d_in[4];
    const float* Wv = (const float*)d_in[5];
    const float* bv = (const float*)d_in[6];
    const float* Wo = (const float*)d_in[7];
    const float* bo = (const float*)d_in[8];
    float* out = (float*)d_out;

    float *qp, *kp, *vp;
    __half *xh, *ahp;
    cudaGetSymbolAddress((void**)&qp, g_q);
    cudaGetSymbolAddress((void**)&kp, g_k);
    cudaGetSymbolAddress((void**)&vp, g_v);
    cudaGetSymbolAddress((void**)&xh, g_xh);
    cudaGetSymbolAddress((void**)&ahp, g_ah);

    cudaFuncSetAttribute(gemm_f16, cudaFuncAttributeMaxDynamicSharedMemorySize, SMEM_DYN);

    const int total = NQ4 + 4 * NW4 + EDIM;
    split_all_kernel<<<(total + 255) / 256, 256>>>(
        (const float4*)query, (const float4*)Wq, (const float4*)Wk,
        (const float4*)Wv, (const float4*)Wo, bq, bk, bv, bo);

    // fused QKV GEMM with softmax epilogue on Q/K
    gemm_f16<<<dim3(12, 64), 256, SMEM_DYN>>>(xh, 0, 1, qp, kp, vp);
    stats_partial_kernel<<<dim3(NCHUNK, 32), 256>>>();
    stats_reduce_kernel<<<(32 * 4224 + 255) / 256, 256>>>();
    combine_kernel<<<dim3(32, 32), 256>>>();
    // O GEMM
    gemm_f16<<<dim3(4, 64), 256, SMEM_DYN>>>(ahp, 3 * EDIM, 0, out, out, out);
}

// round 8
// speedup vs baseline: 1.7038x; 1.2582x over previous
#include <cuda_runtime.h>
#include <cuda_fp16.h>
#include <cstdint>

#define EDIM   512
#define MROWS  8192
#define NCHUNK 16
#define CHUNKS 128

// ---------------- scratch (no allocation allowed) ----------------
__device__ float g_q[MROWS * EDIM];
__device__ float g_k[MROWS * EDIM];
__device__ float g_v[MROWS * EDIM];
__device__ float g_part[32 * NCHUNK * 4224];
__device__ float g_M[32 * 4096];
__device__ float g_ksum[32 * 64];
__device__ float g_vsum[32 * 64];
// fp16 operands (single precision pass)
__device__ __half g_xh[MROWS * EDIM];      // query fp16
__device__ __half g_wh[4 * EDIM * EDIM];   // Wq|Wk|Wv|Wo fp16
__device__ __half g_ah[MROWS * EDIM];      // attention-out fp16
__device__ float g_bp[4 * EDIM];

// =================== helpers ===================
__device__ __forceinline__ uint32_t smem_u32(const void* p) {
    uint32_t a;
    asm("{ .reg .u64 t; cvta.to.shared.u64 t, %1; cvt.u32.u64 %0, t; }" : "=r"(a) : "l"(p));
    return a;
}
__device__ __forceinline__ uint32_t sw128(uint32_t off) { return off ^ ((off >> 3) & 0x70); }

__device__ __forceinline__ uint32_t pack2h(float a, float b) {
    __half2 h = __floats2half2_rn(a, b);
    return *(uint32_t*)&h;
}
#define LDSM4(r, addr) \
    asm volatile("ldmatrix.sync.aligned.m8n8.x4.shared.b16 {%0,%1,%2,%3}, [%4];" \
        : "=r"((r)[0]), "=r"((r)[1]), "=r"((r)[2]), "=r"((r)[3]) : "r"(addr))
#define MMA16816(d, a, b0, b1) \
    asm volatile("mma.sync.aligned.m16n8k16.row.col.f32.f16.f16.f32 " \
        "{%0,%1,%2,%3},{%4,%5,%6,%7},{%8,%9},{%0,%1,%2,%3};" \
        : "+f"((d)[0]), "+f"((d)[1]), "+f"((d)[2]), "+f"((d)[3]) \
        : "r"((a)[0]), "r"((a)[1]), "r"((a)[2]), "r"((a)[3]), "r"(b0), "r"(b1))
#define CP16(saddr, gptr) \
    asm volatile("cp.async.cg.shared.global [%0], [%1], 16;" :: "r"(saddr), "l"(gptr))
#define CP_COMMIT() asm volatile("cp.async.commit_group;" ::: "memory")
#define CP_WAIT2()  asm volatile("cp.async.wait_group 2;" ::: "memory")
#define CP_WAIT1()  asm volatile("cp.async.wait_group 1;" ::: "memory")
#define CP_WAIT0()  asm volatile("cp.async.wait_group 0;" ::: "memory")

// ------------- one fused fp32 -> fp16 conversion for ALL operands -------------
#define NQ4  (MROWS * EDIM / 4)
#define NW4  (EDIM * EDIM / 4)
__global__ void split_all_kernel(const float4* __restrict__ q,
                                 const float4* __restrict__ wq, const float4* __restrict__ wk,
                                 const float4* __restrict__ wv, const float4* __restrict__ wo,
                                 const float* __restrict__ bq, const float* __restrict__ bk,
                                 const float* __restrict__ bv, const float* __restrict__ bo)
{
    const int i = blockIdx.x * blockDim.x + threadIdx.x;
    const int total = NQ4 + 4 * NW4;
    if (i < NQ4) {
        const float4 x = q[i];
        ((uint2*)g_xh)[i] = make_uint2(pack2h(x.x, x.y), pack2h(x.z, x.w));
    } else if (i < total) {
        const int j = i - NQ4;
        const int w = j / NW4, off = j % NW4;
        const float4* src = (w == 0) ? wq : (w == 1) ? wk : (w == 2) ? wv : wo;
        const float4 x = src[off];
        ((uint2*)g_wh)[j] = make_uint2(pack2h(x.x, x.y), pack2h(x.z, x.w));
    } else if (i < total + EDIM) {
        const int t = i - total;
        g_bp[t] = bq[t];
        g_bp[EDIM + t] = bk[t];
        g_bp[2 * EDIM + t] = bv[t];
        g_bp[3 * EDIM + t] = bo[t];
    }
}

// ======== fp16 single-pass warp-MMA GEMM, 3-stage cp.async pipeline ========
// stage = Ah(16K) + Bh(16K) = 32KB, 3 stages = 96KB, occ 2.
#define STAGE_BYTES 32768
#define SMEM_DYN (3 * STAGE_BYTES)

extern __shared__ __align__(1024) char dynsmem[];

__global__ __launch_bounds__(256, 2)
void gemm_f16(const __half* __restrict__ Ah,
              int wbase, int do_softmax,
              float* __restrict__ out0, float* __restrict__ out1, float* __restrict__ out2)
{
    const uint32_t sbase = smem_u32(dynsmem);
    const int tid = threadIdx.x;
    const int wid = tid >> 5, lid = tid & 31;
    const int warp_m = wid >> 2;
    const int warp_n = wid & 3;
    const int nb = blockIdx.x;
    const int bm = blockIdx.y << 7;
    const int bn = (nb & 3) << 7;
    const int sel = nb >> 2;
    float* outp = (sel == 0) ? out0 : ((sel == 1) ? out1 : out2);
    const int wrow = wbase + nb * 128;
    const int fuse_sm = do_softmax && (sel < 2);

    int cp_r[4], cp_cg[4];
    uint32_t cp_soff[4];
    #pragma unroll
    for (int it = 0; it < 4; ++it) {
        const int g = tid + it * 256;
        cp_r[it] = g >> 3;
        cp_cg[it] = g & 7;
        cp_soff[it] = sw128((uint32_t)(cp_r[it] * 128 + cp_cg[it] * 16));
    }

    float acc[4][4][4] = {};
    const int a_row = warp_m * 64 + (lid & 7) + ((lid >> 3) & 1) * 8;
    const int a_kb  = (lid >> 4) * 16;
    const int b_row = warp_n * 32 + (lid & 7) + (lid >> 4) * 8;
    const int b_kb  = ((lid >> 3) & 1) * 16;

    auto issue = [&](int c, int buf) {
        const uint32_t ah = sbase + buf * STAGE_BYTES;
        const uint32_t bh = ah + 16384;
        const int kof = c * 64;
        #pragma unroll
        for (int it = 0; it < 4; ++it) {
            const size_t aoff = (size_t)(bm + cp_r[it]) * EDIM + kof + cp_cg[it] * 8;
            const size_t boff = (size_t)(wrow + cp_r[it]) * EDIM + kof + cp_cg[it] * 8;
            CP16(ah + cp_soff[it], Ah + aoff);
            CP16(bh + cp_soff[it], g_wh + boff);
        }
        CP_COMMIT();
    };

    issue(0, 0);
    issue(1, 1);

    for (int c = 0; c < 8; ++c) {
        if (c + 2 < 8) { issue(c + 2, (c + 2) % 3); CP_WAIT2(); }
        else if (c + 1 < 8) { CP_WAIT1(); }
        else { CP_WAIT0(); }
        __syncthreads();

        const uint32_t ah = sbase + (c % 3) * STAGE_BYTES;
        const uint32_t bh = ah + 16384;

        #pragma unroll
        for (int ks = 0; ks < 4; ++ks) {
            uint32_t Ahf[4][4];
            #pragma unroll
            for (int mt = 0; mt < 4; ++mt) {
                const uint32_t off = sw128((uint32_t)((a_row + mt * 16) * 128 + ks * 32 + a_kb));
                LDSM4(Ahf[mt], ah + off);
            }
            uint32_t Bh[8];
            #pragma unroll
            for (int np = 0; np < 2; ++np) {
                const uint32_t off = sw128((uint32_t)((b_row + np * 16) * 128 + ks * 32 + b_kb));
                LDSM4(&Bh[np * 4], bh + off);
            }
            #pragma unroll
            for (int mt = 0; mt < 4; ++mt)
                #pragma unroll
                for (int nt = 0; nt < 4; ++nt)
                    MMA16816(acc[mt][nt], Ahf[mt], Bh[nt * 2], Bh[nt * 2 + 1]);
        }
        __syncthreads();
    }

    if (fuse_sm) {
        float* sm = (float*)dynsmem;   // 128 rows x stride 130
        #pragma unroll
        for (int mt = 0; mt < 4; ++mt) {
            const int r0 = warp_m * 64 + mt * 16 + (lid >> 2);
            #pragma unroll
            for (int nt = 0; nt < 4; ++nt) {
                const int cit = warp_n * 32 + nt * 8 + ((lid & 3) << 1);
                const float b0 = g_bp[wrow + cit], b1 = g_bp[wrow + cit + 1];
                sm[r0 * 130 + cit]           = acc[mt][nt][0] + b0;
                sm[r0 * 130 + cit + 1]       = acc[mt][nt][1] + b1;
                sm[(r0 + 8) * 130 + cit]     = acc[mt][nt][2] + b0;
                sm[(r0 + 8) * 130 + cit + 1] = acc[mt][nt][3] + b1;
            }
        }
        __syncthreads();
        #pragma unroll
        for (int rr = 0; rr < 16; ++rr) {
            const int r = wid * 16 + rr;
            #pragma unroll
            for (int g = 0; g < 2; ++g) {
                float a = sm[r * 130 + g * 64 + lid];
                float b = sm[r * 130 + g * 64 + lid + 32];
                float m = fmaxf(a, b);
                #pragma unroll
                for (int o = 16; o > 0; o >>= 1)
                    m = fmaxf(m, __shfl_xor_sync(0xffffffffu, m, o));
                float ea = __expf(a - m), eb = __expf(b - m);
                float s = ea + eb;
                #pragma unroll
                for (int o = 16; o > 0; o >>= 1)
                    s += __shfl_xor_sync(0xffffffffu, s, o);
                const float inv = 1.0f / s;
                float* p = outp + (size_t)(bm + r) * EDIM + bn + g * 64;
                p[lid]      = ea * inv;
                p[lid + 32] = eb * inv;
            }
        }
    } else {
        #pragma unroll
        for (int mt = 0; mt < 4; ++mt) {
            const int r0 = bm + warp_m * 64 + mt * 16 + (lid >> 2);
            #pragma unroll
            for (int nt = 0; nt < 4; ++nt) {
                const int cit = warp_n * 32 + nt * 8 + ((lid & 3) << 1);
                const float b0 = g_bp[wrow + cit], b1 = g_bp[wrow + cit + 1];
                const int col = bn + cit;
                float2 o0 = make_float2(acc[mt][nt][0] + b0, acc[mt][nt][1] + b1);
                float2 o1 = make_float2(acc[mt][nt][2] + b0, acc[mt][nt][3] + b1);
                *(float2*)(outp + (size_t)r0 * EDIM + col)       = o0;
                *(float2*)(outp + (size_t)(r0 + 8) * EDIM + col) = o1;
            }
        }
    }
}

// ---------------- per-head partial stats: M = K^T V, Ksum, Vsum -------------
__global__ __launch_bounds__(256)
void stats_partial_kernel()
{
    const int n = blockIdx.y;
    const int b = n >> 3, h = n & 7;
    const int s0 = blockIdx.x * CHUNKS;
    __shared__ float Ks[32][68];
    __shared__ float Vs[32][68];
    const int tid = threadIdx.x;
    const int tx = tid & 15, ty = tid >> 4;
    const int sl = tid >> 3;
    const int dq = (tid & 7) << 3;

    float mreg[4][4] = {};
    float sreg = 0.f;

    for (int st = 0; st < CHUNKS; st += 32) {
        const int s = s0 + st + sl;
        const size_t roff = (size_t)(s * 4 + b) * EDIM + h * 64 + dq;
        const float4 k0 = *(const float4*)(g_k + roff);
        const float4 k1 = *(const float4*)(g_k + roff + 4);
        const float4 v0 = *(const float4*)(g_v + roff);
        const float4 v1 = *(const float4*)(g_v + roff + 4);
        __syncthreads();
        *(float4*)&Ks[sl][dq]     = k0;
        *(float4*)&Ks[sl][dq + 4] = k1;
        *(float4*)&Vs[sl][dq]     = v0;
        *(float4*)&Vs[sl][dq + 4] = v1;
        __syncthreads();
        #pragma unroll
        for (int ss = 0; ss < 32; ++ss) {
            float kf[4], vf[4];
            *(float4*)kf = *(const float4*)&Ks[ss][ty * 4];
            *(float4*)vf = *(const float4*)&Vs[ss][tx * 4];
            #pragma unroll
            for (int i = 0; i < 4; ++i)
                #pragma unroll
                for (int j = 0; j < 4; ++j)
                    mreg[i][j] += kf[i] * vf[j];
        }
        if (tid < 64) {
            #pragma unroll
            for (int ss = 0; ss < 32; ++ss) sreg += Ks[ss][tid];
        } else if (tid < 128) {
            #pragma unroll
            for (int ss = 0; ss < 32; ++ss) sreg += Vs[ss][tid - 64];
        }
    }
    float* pb = g_part + (size_t)(n * NCHUNK + blockIdx.x) * 4224;
    #pragma unroll
    for (int i = 0; i < 4; ++i) {
        float4 w;
        w.x = mreg[i][0]; w.y = mreg[i][1]; w.z = mreg[i][2]; w.w = mreg[i][3];
        *(float4*)(pb + (ty * 4 + i) * 64 + tx * 4) = w;
    }
    if (tid < 128) pb[4096 + tid] = sreg;
}

// parallel reduce: one thread per output element
__global__ void stats_reduce_kernel()
{
    const int i = blockIdx.x * 256 + threadIdx.x;
    if (i >= 32 * 4224) return;
    const int n = i / 4224, j = i % 4224;
    float s = 0.f;
    #pragma unroll
    for (int c = 0; c < NCHUNK; ++c)
        s += g_part[(size_t)(n * NCHUNK + c) * 4224 + j];
    if (j < 4096)       g_M[n * 4096 + j] = s;
    else if (j < 4160)  g_ksum[n * 64 + (j - 4096)] = s;
    else                g_vsum[n * 64 + (j - 4160)] = s;
}

// ---- combine: a = (62*Vsum + 2*q@M) / (62*2048 + 2*q.Ksum), emit fp16 ----
__global__ __launch_bounds__(256)
void combine_kernel()
{
    const int n = blockIdx.y;
    const int b = n >> 3, h = n & 7;
    const int l0 = blockIdx.x << 6;
    __shared__ float Ms[64][64];
    __shared__ float Qs[64][65];
    __shared__ float ksum_s[64], vsum_s[64], den_s[64];
    const int tid = threadIdx.x;

    {
        const float4* Mp = (const float4*)(g_M + (size_t)n * 4096);
        float4* Md = (float4*)&Ms[0][0];
        for (int i = tid; i < 1024; i += 256) Md[i] = Mp[i];
    }
    if (tid < 64) { ksum_s[tid] = g_ksum[n * 64 + tid]; vsum_s[tid] = g_vsum[n * 64 + tid]; }
    {
        const int l = tid >> 2;
        const int dq = (tid & 3) << 4;
        const float* qr = g_q + (size_t)((l0 + l) * 4 + b) * EDIM + h * 64 + dq;
        #pragma unroll
        for (int u = 0; u < 16; u += 4) {
            const float4 qv = *(const float4*)(qr + u);
            Qs[dq + u + 0][l] = qv.x; Qs[dq + u + 1][l] = qv.y;
            Qs[dq + u + 2][l] = qv.z; Qs[dq + u + 3][l] = qv.w;
        }
    }
    __syncthreads();
    if (tid < 64) {
        float s = 0.f;
        #pragma unroll
        for (int d = 0; d < 64; ++d) s += Qs[d][tid] * ksum_s[d];
        den_s[tid] = 1.0f / (126976.0f + 2.0f * s);
    }
    __syncthreads();
    const int tx = tid & 15, ty = tid >> 4;
    float acc[4][4] = {};
    #pragma unroll
    for (int d = 0; d < 64; ++d) {
        float qf[4], mf[4];
        #pragma unroll
        for (int i = 0; i < 4; ++i) qf[i] = Qs[d][ty * 4 + i];
        *(float4*)mf = *(const float4*)&Ms[d][tx * 4];
        #pragma unroll
        for (int i = 0; i < 4; ++i)
            #pragma unroll
            for (int j = 0; j < 4; ++j)
                acc[i][j] += qf[i] * mf[j];
    }
    #pragma unroll
    for (int i = 0; i < 4; ++i) {
        const int l = ty * 4 + i;
        const float inv = den_s[l];
        float ox = (62.f * vsum_s[tx * 4 + 0] + 2.f * acc[i][0]) * inv;
        float oy = (62.f * vsum_s[tx * 4 + 1] + 2.f * acc[i][1]) * inv;
        float oz = (62.f * vsum_s[tx * 4 + 2] + 2.f * acc[i][2]) * inv;
        float ow = (62.f * vsum_s[tx * 4 + 3] + 2.f * acc[i][3]) * inv;
        const size_t off = (size_t)((l0 + l) * 4 + b) * EDIM + h * 64 + tx * 4;
        *(uint2*)(g_ah + off) = make_uint2(pack2h(ox, oy), pack2h(oz, ow));
    }
}

// ---------------- launch -----------------------------------------------------
extern "C" void kernel_launch(void* const* d_in, const int* in_sizes, int n_in,
                              void* d_out, int out_size)
{
    const float* query = (const float*)d_in[0];
    const float* Wq = (const float*)d_in[1];
    const float* bq = (const float*)d_in[2];
    const float* Wk = (const float*)d_in[3];
    const float* bk = (const float*)d_in[4];
    const float* Wv = (const float*)d_in[5];
    const float* bv = (const float*)d_in[6];
    const float* Wo = (const float*)d_in[7];
    const float* bo = (const float*)d_in[8];
    float* out = (float*)d_out;

    float *qp, *kp, *vp;
    __half *xh, *ahp;
    cudaGetSymbolAddress((void**)&qp, g_q);
    cudaGetSymbolAddress((void**)&kp, g_k);
    cudaGetSymbolAddress((void**)&vp, g_v);
    cudaGetSymbolAddress((void**)&xh, g_xh);
    cudaGetSymbolAddress((void**)&ahp, g_ah);

    cudaFuncSetAttribute(gemm_f16, cudaFuncAttributeMaxDynamicSharedMemorySize, SMEM_DYN);

    const int total = NQ4 + 4 * NW4 + EDIM;
    split_all_kernel<<<(total + 255) / 256, 256>>>(
        (const float4*)query, (const float4*)Wq, (const float4*)Wk,
        (const float4*)Wv, (const float4*)Wo, bq, bk, bv, bo);

    // fused QKV GEMM with softmax epilogue on Q/K
    gemm_f16<<<dim3(12, 64), 256, SMEM_DYN>>>(xh, 0, 1, qp, kp, vp);
    stats_partial_kernel<<<dim3(NCHUNK, 32), 256>>>();
    stats_reduce_kernel<<<(32 * 4224 + 255) / 256, 256>>>();
    combine_kernel<<<dim3(32, 32), 256>>>();
    // O GEMM
    gemm_f16<<<dim3(4, 64), 256, SMEM_DYN>>>(ahp, 3 * EDIM, 0, out, out, out);
}

// round 9
// speedup vs baseline: 2.0156x; 1.1830x over previous
#include <cuda_runtime.h>
#include <cuda_fp16.h>
#include <cstdint>

#define EDIM   512
#define MROWS  8192
#define NCHUNK 8
#define S_PER_CHUNK 256
#define S_TILE 64

// ---------------- scratch (no allocation allowed) ----------------
__device__ __half g_qh[MROWS * EDIM];
__device__ __half g_kh[MROWS * EDIM];
__device__ __half g_vh[MROWS * EDIM];
__device__ float g_part[32 * NCHUNK * 4224];
__device__ float g_M[32 * 4096];
__device__ float g_ksum[32 * 64];
__device__ float g_vsum[32 * 64];
__device__ __half g_xh[MROWS * EDIM];      // query fp16
__device__ __half g_wh[4 * EDIM * EDIM];   // Wq|Wk|Wv|Wo fp16
__device__ __half g_ah[MROWS * EDIM];      // attention-out fp16
__device__ float g_bp[4 * EDIM];

// =================== helpers ===================
__device__ __forceinline__ uint32_t smem_u32(const void* p) {
    uint32_t a;
    asm("{ .reg .u64 t; cvta.to.shared.u64 t, %1; cvt.u32.u64 %0, t; }" : "=r"(a) : "l"(p));
    return a;
}
__device__ __forceinline__ uint32_t sw128(uint32_t off) { return off ^ ((off >> 3) & 0x70); }

__device__ __forceinline__ uint32_t pack2h(float a, float b) {
    __half2 h = __floats2half2_rn(a, b);
    return *(uint32_t*)&h;
}
#define LDSM4(r, addr) \
    asm volatile("ldmatrix.sync.aligned.m8n8.x4.shared.b16 {%0,%1,%2,%3}, [%4];" \
        : "=r"((r)[0]), "=r"((r)[1]), "=r"((r)[2]), "=r"((r)[3]) : "r"(addr))
#define LDSM4T(r, addr) \
    asm volatile("ldmatrix.sync.aligned.m8n8.x4.trans.shared.b16 {%0,%1,%2,%3}, [%4];" \
        : "=r"((r)[0]), "=r"((r)[1]), "=r"((r)[2]), "=r"((r)[3]) : "r"(addr))
#define MMA16816(d, a, b0, b1) \
    asm volatile("mma.sync.aligned.m16n8k16.row.col.f32.f16.f16.f32 " \
        "{%0,%1,%2,%3},{%4,%5,%6,%7},{%8,%9},{%0,%1,%2,%3};" \
        : "+f"((d)[0]), "+f"((d)[1]), "+f"((d)[2]), "+f"((d)[3]) \
        : "r"((a)[0]), "r"((a)[1]), "r"((a)[2]), "r"((a)[3]), "r"(b0), "r"(b1))
#define CP16(saddr, gptr) \
    asm volatile("cp.async.cg.shared.global [%0], [%1], 16;" :: "r"(saddr), "l"(gptr))
#define CP_COMMIT() asm volatile("cp.async.commit_group;" ::: "memory")
#define CP_WAIT2()  asm volatile("cp.async.wait_group 2;" ::: "memory")
#define CP_WAIT1()  asm volatile("cp.async.wait_group 1;" ::: "memory")
#define CP_WAIT0()  asm volatile("cp.async.wait_group 0;" ::: "memory")

// ------------- one fused fp32 -> fp16 conversion for ALL operands -------------
#define NQ4  (MROWS * EDIM / 4)
#define NW4  (EDIM * EDIM / 4)
__global__ void split_all_kernel(const float4* __restrict__ q,
                                 const float4* __restrict__ wq, const float4* __restrict__ wk,
                                 const float4* __restrict__ wv, const float4* __restrict__ wo,
                                 const float* __restrict__ bq, const float* __restrict__ bk,
                                 const float* __restrict__ bv, const float* __restrict__ bo)
{
    const int i = blockIdx.x * blockDim.x + threadIdx.x;
    const int total = NQ4 + 4 * NW4;
    if (i < NQ4) {
        const float4 x = q[i];
        ((uint2*)g_xh)[i] = make_uint2(pack2h(x.x, x.y), pack2h(x.z, x.w));
    } else if (i < total) {
        const int j = i - NQ4;
        const int w = j / NW4, off = j % NW4;
        const float4* src = (w == 0) ? wq : (w == 1) ? wk : (w == 2) ? wv : wo;
        const float4 x = src[off];
        ((uint2*)g_wh)[j] = make_uint2(pack2h(x.x, x.y), pack2h(x.z, x.w));
    } else if (i < total + EDIM) {
        const int t = i - total;
        g_bp[t] = bq[t];
        g_bp[EDIM + t] = bk[t];
        g_bp[2 * EDIM + t] = bv[t];
        g_bp[3 * EDIM + t] = bo[t];
    }
}

// ======== fp16 single-pass warp-MMA GEMM, 3-stage cp.async pipeline ========
#define STAGE_BYTES 32768
#define SMEM_DYN (3 * STAGE_BYTES)

extern __shared__ __align__(1024) char dynsmem[];

__global__ __launch_bounds__(256, 2)
void gemm_f16(const __half* __restrict__ Ah,
              int wbase, int do_softmax,
              void* __restrict__ out0, void* __restrict__ out1, void* __restrict__ out2)
{
    const uint32_t sbase = smem_u32(dynsmem);
    const int tid = threadIdx.x;
    const int wid = tid >> 5, lid = tid & 31;
    const int warp_m = wid >> 2;
    const int warp_n = wid & 3;
    const int nb = blockIdx.x;
    const int bm = blockIdx.y << 7;
    const int bn = (nb & 3) << 7;
    const int sel = nb >> 2;
    void* outp = (sel == 0) ? out0 : ((sel == 1) ? out1 : out2);
    const int wrow = wbase + nb * 128;
    const int fuse_sm = do_softmax && (sel < 2);

    int cp_r[4], cp_cg[4];
    uint32_t cp_soff[4];
    #pragma unroll
    for (int it = 0; it < 4; ++it) {
        const int g = tid + it * 256;
        cp_r[it] = g >> 3;
        cp_cg[it] = g & 7;
        cp_soff[it] = sw128((uint32_t)(cp_r[it] * 128 + cp_cg[it] * 16));
    }

    float acc[4][4][4] = {};
    const int a_row = warp_m * 64 + (lid & 7) + ((lid >> 3) & 1) * 8;
    const int a_kb  = (lid >> 4) * 16;
    const int b_row = warp_n * 32 + (lid & 7) + (lid >> 4) * 8;
    const int b_kb  = ((lid >> 3) & 1) * 16;

    auto issue = [&](int c, int buf) {
        const uint32_t ah = sbase + buf * STAGE_BYTES;
        const uint32_t bh = ah + 16384;
        const int kof = c * 64;
        #pragma unroll
        for (int it = 0; it < 4; ++it) {
            const size_t aoff = (size_t)(bm + cp_r[it]) * EDIM + kof + cp_cg[it] * 8;
            const size_t boff = (size_t)(wrow + cp_r[it]) * EDIM + kof + cp_cg[it] * 8;
            CP16(ah + cp_soff[it], Ah + aoff);
            CP16(bh + cp_soff[it], g_wh + boff);
        }
        CP_COMMIT();
    };

    issue(0, 0);
    issue(1, 1);

    for (int c = 0; c < 8; ++c) {
        if (c + 2 < 8) { issue(c + 2, (c + 2) % 3); CP_WAIT2(); }
        else if (c + 1 < 8) { CP_WAIT1(); }
        else { CP_WAIT0(); }
        __syncthreads();

        const uint32_t ah = sbase + (c % 3) * STAGE_BYTES;
        const uint32_t bh = ah + 16384;

        #pragma unroll
        for (int ks = 0; ks < 4; ++ks) {
            uint32_t Ahf[4][4];
            #pragma unroll
            for (int mt = 0; mt < 4; ++mt) {
                const uint32_t off = sw128((uint32_t)((a_row + mt * 16) * 128 + ks * 32 + a_kb));
                LDSM4(Ahf[mt], ah + off);
            }
            uint32_t Bh[8];
            #pragma unroll
            for (int np = 0; np < 2; ++np) {
                const uint32_t off = sw128((uint32_t)((b_row + np * 16) * 128 + ks * 32 + b_kb));
                LDSM4(&Bh[np * 4], bh + off);
            }
            #pragma unroll
            for (int mt = 0; mt < 4; ++mt)
                #pragma unroll
                for (int nt = 0; nt < 4; ++nt)
                    MMA16816(acc[mt][nt], Ahf[mt], Bh[nt * 2], Bh[nt * 2 + 1]);
        }
        __syncthreads();
    }

    if (fuse_sm) {
        float* sm = (float*)dynsmem;   // 128 rows x stride 130
        #pragma unroll
        for (int mt = 0; mt < 4; ++mt) {
            const int r0 = warp_m * 64 + mt * 16 + (lid >> 2);
            #pragma unroll
            for (int nt = 0; nt < 4; ++nt) {
                const int cit = warp_n * 32 + nt * 8 + ((lid & 3) << 1);
                const float b0 = g_bp[wrow + cit], b1 = g_bp[wrow + cit + 1];
                sm[r0 * 130 + cit]           = acc[mt][nt][0] + b0;
                sm[r0 * 130 + cit + 1]       = acc[mt][nt][1] + b1;
                sm[(r0 + 8) * 130 + cit]     = acc[mt][nt][2] + b0;
                sm[(r0 + 8) * 130 + cit + 1] = acc[mt][nt][3] + b1;
            }
        }
        __syncthreads();
        __half* op = (__half*)outp;
        #pragma unroll
        for (int rr = 0; rr < 16; ++rr) {
            const int r = wid * 16 + rr;
            #pragma unroll
            for (int g = 0; g < 2; ++g) {
                float a = sm[r * 130 + g * 64 + lid];
                float b = sm[r * 130 + g * 64 + lid + 32];
                float m = fmaxf(a, b);
                #pragma unroll
                for (int o = 16; o > 0; o >>= 1)
                    m = fmaxf(m, __shfl_xor_sync(0xffffffffu, m, o));
                float ea = __expf(a - m), eb = __expf(b - m);
                float s = ea + eb;
                #pragma unroll
                for (int o = 16; o > 0; o >>= 1)
                    s += __shfl_xor_sync(0xffffffffu, s, o);
                const float inv = 1.0f / s;
                __half* p = op + (size_t)(bm + r) * EDIM + bn + g * 64;
                p[lid]      = __float2half_rn(ea * inv);
                p[lid + 32] = __float2half_rn(eb * inv);
            }
        }
    } else if (do_softmax) {
        // V output: fp16
        __half* op = (__half*)outp;
        #pragma unroll
        for (int mt = 0; mt < 4; ++mt) {
            const int r0 = bm + warp_m * 64 + mt * 16 + (lid >> 2);
            #pragma unroll
            for (int nt = 0; nt < 4; ++nt) {
                const int cit = warp_n * 32 + nt * 8 + ((lid & 3) << 1);
                const float b0 = g_bp[wrow + cit], b1 = g_bp[wrow + cit + 1];
                const int col = bn + cit;
                *(__half2*)(op + (size_t)r0 * EDIM + col) =
                    __floats2half2_rn(acc[mt][nt][0] + b0, acc[mt][nt][1] + b1);
                *(__half2*)(op + (size_t)(r0 + 8) * EDIM + col) =
                    __floats2half2_rn(acc[mt][nt][2] + b0, acc[mt][nt][3] + b1);
            }
        }
    } else {
        float* op = (float*)outp;
        #pragma unroll
        for (int mt = 0; mt < 4; ++mt) {
            const int r0 = bm + warp_m * 64 + mt * 16 + (lid >> 2);
            #pragma unroll
            for (int nt = 0; nt < 4; ++nt) {
                const int cit = warp_n * 32 + nt * 8 + ((lid & 3) << 1);
                const float b0 = g_bp[wrow + cit], b1 = g_bp[wrow + cit + 1];
                const int col = bn + cit;
                *(float2*)(op + (size_t)r0 * EDIM + col) =
                    make_float2(acc[mt][nt][0] + b0, acc[mt][nt][1] + b1);
                *(float2*)(op + (size_t)(r0 + 8) * EDIM + col) =
                    make_float2(acc[mt][nt][2] + b0, acc[mt][nt][3] + b1);
            }
        }
    }
}

// ======== MMA stats: per head, M = K^T V (64x64), ksum, vsum ========
// grid (NCHUNK, 32), 256 thr. K,V tiles 64s x 64d fp16, double buffered.
__global__ __launch_bounds__(256, 2)
void stats_mma_kernel()
{
    __shared__ __align__(1024) char smem[2 * 16384];  // 2 bufs x (K 8K + V 8K)
    const int n = blockIdx.y, b = n >> 3, h = n & 7;
    const int s0 = blockIdx.x * S_PER_CHUNK;
    const uint32_t sb = smem_u32(smem);
    const int tid = threadIdx.x, wid = tid >> 5, lid = tid & 31;
    const int warp_m = wid >> 2;    // d1 half (32 rows)
    const int warp_n = wid & 3;     // d2 quarter (16 cols)

    auto issue = [&](int t, int buf) {
        const uint32_t kb = sb + buf * 16384;
        const uint32_t vb = kb + 8192;
        #pragma unroll
        for (int it = 0; it < 2; ++it) {
            const int g = tid + it * 256;
            const int r = g >> 3, cg = g & 7;
            const int s = s0 + t * S_TILE + r;
            const size_t go = (size_t)(s * 4 + b) * EDIM + h * 64 + cg * 8;
            const uint32_t so = sw128((uint32_t)(r * 128 + cg * 16));
            CP16(kb + so, g_kh + go);
            CP16(vb + so, g_vh + go);
        }
        CP_COMMIT();
    };

    float acc[2][2][4] = {};
    float ksum = 0.f, vsum = 0.f;

    // trans-ldsm lane addresses
    // A from K: bit3 -> d-half (byte +16), bit4 -> s-half (row +8)
    const int a_row = (lid & 7) + ((lid >> 4) & 1) * 8;
    const int a_by  = ((lid >> 3) & 1) * 16;
    // B from V: bit3 -> s-half (row +8), bit4 -> n-half (byte +16)
    const int b_row = (lid & 7) + ((lid >> 3) & 1) * 8;
    const int b_by  = ((lid >> 4) & 1) * 16;

    issue(0, 0);
    issue(1, 1);

    const int NT = S_PER_CHUNK / S_TILE;   // 4
    for (int t = 0; t < NT; ++t) {
        if (t < NT - 1) CP_WAIT1(); else CP_WAIT0();
        __syncthreads();
        const uint32_t kb = sb + (t & 1) * 16384;
        const uint32_t vb = kb + 8192;

        #pragma unroll
        for (int ks = 0; ks < 4; ++ks) {
            uint32_t Af[2][4];
            #pragma unroll
            for (int mt = 0; mt < 2; ++mt) {
                const uint32_t off = sw128((uint32_t)((ks * 16 + a_row) * 128
                                     + warp_m * 64 + mt * 32 + a_by));
                LDSM4T(Af[mt], kb + off);
            }
            uint32_t Bf[4];
            {
                const uint32_t off = sw128((uint32_t)((ks * 16 + b_row) * 128
                                     + warp_n * 32 + b_by));
                LDSM4T(Bf, vb + off);
            }
            #pragma unroll
            for (int mt = 0; mt < 2; ++mt)
                #pragma unroll
                for (int nt = 0; nt < 2; ++nt)
                    MMA16816(acc[mt][nt], Af[mt], Bf[nt * 2], Bf[nt * 2 + 1]);
        }

        // column sums (threads 0-127)
        if (tid < 128) {
            const uint32_t base = (tid < 64) ? kb : vb;
            const int d = tid & 63;
            float s = 0.f;
            #pragma unroll
            for (int r = 0; r < 64; ++r)
                s += __half2float(*(const __half*)(smem + (base - sb) + sw128((uint32_t)(r * 128 + d * 2))));
            if (tid < 64) ksum += s; else vsum += s;
        }
        __syncthreads();
        if (t + 2 < NT) issue(t + 2, t & 1);
    }

    float* pb = g_part + (size_t)(n * NCHUNK + blockIdx.x) * 4224;
    #pragma unroll
    for (int mt = 0; mt < 2; ++mt) {
        const int d1 = warp_m * 32 + mt * 16 + (lid >> 2);
        #pragma unroll
        for (int nt = 0; nt < 2; ++nt) {
            const int d2 = warp_n * 16 + nt * 8 + ((lid & 3) << 1);
            *(float2*)(pb + d1 * 64 + d2)       = make_float2(acc[mt][nt][0], acc[mt][nt][1]);
            *(float2*)(pb + (d1 + 8) * 64 + d2) = make_float2(acc[mt][nt][2], acc[mt][nt][3]);
        }
    }
    if (tid < 64)        pb[4096 + tid] = ksum;
    else if (tid < 128)  pb[4096 + tid] = vsum;
}

// parallel reduce: one thread per output element
__global__ void stats_reduce_kernel()
{
    const int i = blockIdx.x * 256 + threadIdx.x;
    if (i >= 32 * 4224) return;
    const int n = i / 4224, j = i % 4224;
    float s = 0.f;
    #pragma unroll
    for (int c = 0; c < NCHUNK; ++c)
        s += g_part[(size_t)(n * NCHUNK + c) * 4224 + j];
    if (j < 4096)       g_M[n * 4096 + j] = s;
    else if (j < 4160)  g_ksum[n * 64 + (j - 4096)] = s;
    else                g_vsum[n * 64 + (j - 4160)] = s;
}

// ---- combine: a = (62*Vsum + 2*q@M) / (62*2048 + 2*q.Ksum), emit fp16 ----
__global__ __launch_bounds__(256)
void combine_kernel()
{
    const int n = blockIdx.y;
    const int b = n >> 3, h = n & 7;
    const int l0 = blockIdx.x << 6;
    __shared__ float Ms[64][64];
    __shared__ float Qs[64][65];
    __shared__ float ksum_s[64], vsum_s[64], den_s[64];
    const int tid = threadIdx.x;

    {
        const float4* Mp = (const float4*)(g_M + (size_t)n * 4096);
        float4* Md = (float4*)&Ms[0][0];
        for (int i = tid; i < 1024; i += 256) Md[i] = Mp[i];
    }
    if (tid < 64) { ksum_s[tid] = g_ksum[n * 64 + tid]; vsum_s[tid] = g_vsum[n * 64 + tid]; }
    {
        const int l = tid >> 2;
        const int dq = (tid & 3) << 4;
        const __half* qr = g_qh + (size_t)((l0 + l) * 4 + b) * EDIM + h * 64 + dq;
        #pragma unroll
        for (int u = 0; u < 16; u += 8) {
            const uint4 uv = *(const uint4*)(qr + u);
            const uint32_t w[4] = {uv.x, uv.y, uv.z, uv.w};
            #pragma unroll
            for (int p = 0; p < 4; ++p) {
                const float2 f = __half22float2(*(const __half2*)&w[p]);
                Qs[dq + u + p * 2 + 0][l] = f.x;
                Qs[dq + u + p * 2 + 1][l] = f.y;
            }
        }
    }
    __syncthreads();
    if (tid < 64) {
        float s = 0.f;
        #pragma unroll
        for (int d = 0; d < 64; ++d) s += Qs[d][tid] * ksum_s[d];
        den_s[tid] = 1.0f / (126976.0f + 2.0f * s);
    }
    __syncthreads();
    const int tx = tid & 15, ty = tid >> 4;
    float acc[4][4] = {};
    #pragma unroll
    for (int d = 0; d < 64; ++d) {
        float qf[4], mf[4];
        #pragma unroll
        for (int i = 0; i < 4; ++i) qf[i] = Qs[d][ty * 4 + i];
        *(float4*)mf = *(const float4*)&Ms[d][tx * 4];
        #pragma unroll
        for (int i = 0; i < 4; ++i)
            #pragma unroll
            for (int j = 0; j < 4; ++j)
                acc[i][j] += qf[i] * mf[j];
    }
    #pragma unroll
    for (int i = 0; i < 4; ++i) {
        const int l = ty * 4 + i;
        const float inv = den_s[l];
        float ox = (62.f * vsum_s[tx * 4 + 0] + 2.f * acc[i][0]) * inv;
        float oy = (62.f * vsum_s[tx * 4 + 1] + 2.f * acc[i][1]) * inv;
        float oz = (62.f * vsum_s[tx * 4 + 2] + 2.f * acc[i][2]) * inv;
        float ow = (62.f * vsum_s[tx * 4 + 3] + 2.f * acc[i][3]) * inv;
        const size_t off = (size_t)((l0 + l) * 4 + b) * EDIM + h * 64 + tx * 4;
        *(uint2*)(g_ah + off) = make_uint2(pack2h(ox, oy), pack2h(oz, ow));
    }
}

// ---------------- launch -----------------------------------------------------
extern "C" void kernel_launch(void* const* d_in, const int* in_sizes, int n_in,
                              void* d_out, int out_size)
{
    const float* query = (const float*)d_in[0];
    const float* Wq = (const float*)d_in[1];
    const float* bq = (const float*)d_in[2];
    const float* Wk = (const float*)d_in[3];
    const float* bk = (const float*)d_in[4];
    const float* Wv = (const float*)d_in[5];
    const float* bv = (const float*)d_in[6];
    const float* Wo = (const float*)d_in[7];
    const float* bo = (const float*)d_in[8];
    float* out = (float*)d_out;

    __half *qp, *kp, *vp, *xh, *ahp;
    cudaGetSymbolAddress((void**)&qp, g_qh);
    cudaGetSymbolAddress((void**)&kp, g_kh);
    cudaGetSymbolAddress((void**)&vp, g_vh);
    cudaGetSymbolAddress((void**)&xh, g_xh);
    cudaGetSymbolAddress((void**)&ahp, g_ah);

    cudaFuncSetAttribute(gemm_f16, cudaFuncAttributeMaxDynamicSharedMemorySize, SMEM_DYN);

    const int total = NQ4 + 4 * NW4 + EDIM;
    split_all_kernel<<<(total + 255) / 256, 256>>>(
        (const float4*)query, (const float4*)Wq, (const float4*)Wk,
        (const float4*)Wv, (const float4*)Wo, bq, bk, bv, bo);

    // fused QKV GEMM with softmax epilogue on Q/K, fp16 outputs
    gemm_f16<<<dim3(12, 64), 256, SMEM_DYN>>>(xh, 0, 1, qp, kp, vp);
    stats_mma_kernel<<<dim3(NCHUNK, 32), 256>>>();
    stats_reduce_kernel<<<(32 * 4224 + 255) / 256, 256>>>();
    combine_kernel<<<dim3(32, 32), 256>>>();
    // O GEMM (fp32 output)
    gemm_f16<<<dim3(4, 64), 256, SMEM_DYN>>>(ahp, 3 * EDIM, 0, out, out, out);
}

// round 10
// speedup vs baseline: 2.0322x; 1.0083x over previous
#include <cuda_runtime.h>
#include <cuda_fp16.h>
#include <cstdint>

#define EDIM   512
#define MROWS  8192
#define NCHUNK 4
#define S_PER_CHUNK 512
#define S_TILE 64

// ---------------- scratch (no allocation allowed) ----------------
__device__ __half g_qh[MROWS * EDIM];
__device__ __half g_kh[MROWS * EDIM];
__device__ __half g_vh[MROWS * EDIM];
__device__ float g_part[32 * NCHUNK * 4224];
__device__ __half g_Mh[32 * 4096];
__device__ float g_ksum[32 * 64];
__device__ float g_vsum[32 * 64];
__device__ unsigned g_cnt[32];             // zero-init; self-resetting
__device__ __half g_xh[MROWS * EDIM];      // query fp16
__device__ __half g_wh[4 * EDIM * EDIM];   // Wq|Wk|Wv|Wo fp16
__device__ __half g_ah[MROWS * EDIM];      // attention-out fp16
__device__ float g_bp[4 * EDIM];

// =================== helpers ===================
__device__ __forceinline__ uint32_t smem_u32(const void* p) {
    uint32_t a;
    asm("{ .reg .u64 t; cvta.to.shared.u64 t, %1; cvt.u32.u64 %0, t; }" : "=r"(a) : "l"(p));
    return a;
}
__device__ __forceinline__ uint32_t sw128(uint32_t off) { return off ^ ((off >> 3) & 0x70); }

__device__ __forceinline__ uint32_t pack2h(float a, float b) {
    __half2 h = __floats2half2_rn(a, b);
    return *(uint32_t*)&h;
}
#define LDSM4(r, addr) \
    asm volatile("ldmatrix.sync.aligned.m8n8.x4.shared.b16 {%0,%1,%2,%3}, [%4];" \
        : "=r"((r)[0]), "=r"((r)[1]), "=r"((r)[2]), "=r"((r)[3]) : "r"(addr))
#define LDSM4T(r, addr) \
    asm volatile("ldmatrix.sync.aligned.m8n8.x4.trans.shared.b16 {%0,%1,%2,%3}, [%4];" \
        : "=r"((r)[0]), "=r"((r)[1]), "=r"((r)[2]), "=r"((r)[3]) : "r"(addr))
#define MMA16816(d, a, b0, b1) \
    asm volatile("mma.sync.aligned.m16n8k16.row.col.f32.f16.f16.f32 " \
        "{%0,%1,%2,%3},{%4,%5,%6,%7},{%8,%9},{%0,%1,%2,%3};" \
        : "+f"((d)[0]), "+f"((d)[1]), "+f"((d)[2]), "+f"((d)[3]) \
        : "r"((a)[0]), "r"((a)[1]), "r"((a)[2]), "r"((a)[3]), "r"(b0), "r"(b1))
#define CP16(saddr, gptr) \
    asm volatile("cp.async.cg.shared.global [%0], [%1], 16;" :: "r"(saddr), "l"(gptr))
#define CP_COMMIT() asm volatile("cp.async.commit_group;" ::: "memory")
#define CP_WAIT2()  asm volatile("cp.async.wait_group 2;" ::: "memory")
#define CP_WAIT1()  asm volatile("cp.async.wait_group 1;" ::: "memory")
#define CP_WAIT0()  asm volatile("cp.async.wait_group 0;" ::: "memory")

// ------------- one fused fp32 -> fp16 conversion for ALL operands -------------
#define NQ4  (MROWS * EDIM / 4)
#define NW4  (EDIM * EDIM / 4)
__global__ void split_all_kernel(const float4* __restrict__ q,
                                 const float4* __restrict__ wq, const float4* __restrict__ wk,
                                 const float4* __restrict__ wv, const float4* __restrict__ wo,
                                 const float* __restrict__ bq, const float* __restrict__ bk,
                                 const float* __restrict__ bv, const float* __restrict__ bo)
{
    const int i = blockIdx.x * blockDim.x + threadIdx.x;
    const int total = NQ4 + 4 * NW4;
    if (i < NQ4) {
        const float4 x = q[i];
        ((uint2*)g_xh)[i] = make_uint2(pack2h(x.x, x.y), pack2h(x.z, x.w));
    } else if (i < total) {
        const int j = i - NQ4;
        const int w = j / NW4, off = j % NW4;
        const float4* src = (w == 0) ? wq : (w == 1) ? wk : (w == 2) ? wv : wo;
        const float4 x = src[off];
        ((uint2*)g_wh)[j] = make_uint2(pack2h(x.x, x.y), pack2h(x.z, x.w));
    } else if (i < total + EDIM) {
        const int t = i - total;
        g_bp[t] = bq[t];
        g_bp[EDIM + t] = bk[t];
        g_bp[2 * EDIM + t] = bv[t];
        g_bp[3 * EDIM + t] = bo[t];
    }
}

// ======== fp16 single-pass warp-MMA GEMM, 3-stage cp.async pipeline ========
#define STAGE_BYTES 32768
#define SMEM_DYN (3 * STAGE_BYTES)

extern __shared__ __align__(1024) char dynsmem[];

__global__ __launch_bounds__(256, 2)
void gemm_f16(const __half* __restrict__ Ah,
              int wbase, int do_softmax,
              void* __restrict__ out0, void* __restrict__ out1, void* __restrict__ out2)
{
    const uint32_t sbase = smem_u32(dynsmem);
    const int tid = threadIdx.x;
    const int wid = tid >> 5, lid = tid & 31;
    const int warp_m = wid >> 2;
    const int warp_n = wid & 3;
    const int nb = blockIdx.x;
    const int bm = blockIdx.y << 7;
    const int bn = (nb & 3) << 7;
    const int sel = nb >> 2;
    void* outp = (sel == 0) ? out0 : ((sel == 1) ? out1 : out2);
    const int wrow = wbase + nb * 128;
    const int fuse_sm = do_softmax && (sel < 2);

    int cp_r[4], cp_cg[4];
    uint32_t cp_soff[4];
    #pragma unroll
    for (int it = 0; it < 4; ++it) {
        const int g = tid + it * 256;
        cp_r[it] = g >> 3;
        cp_cg[it] = g & 7;
        cp_soff[it] = sw128((uint32_t)(cp_r[it] * 128 + cp_cg[it] * 16));
    }

    float acc[4][4][4] = {};
    const int a_row = warp_m * 64 + (lid & 7) + ((lid >> 3) & 1) * 8;
    const int a_kb  = (lid >> 4) * 16;
    const int b_row = warp_n * 32 + (lid & 7) + (lid >> 4) * 8;
    const int b_kb  = ((lid >> 3) & 1) * 16;

    auto issue = [&](int c, int buf) {
        const uint32_t ah = sbase + buf * STAGE_BYTES;
        const uint32_t bh = ah + 16384;
        const int kof = c * 64;
        #pragma unroll
        for (int it = 0; it < 4; ++it) {
            const size_t aoff = (size_t)(bm + cp_r[it]) * EDIM + kof + cp_cg[it] * 8;
            const size_t boff = (size_t)(wrow + cp_r[it]) * EDIM + kof + cp_cg[it] * 8;
            CP16(ah + cp_soff[it], Ah + aoff);
            CP16(bh + cp_soff[it], g_wh + boff);
        }
        CP_COMMIT();
    };

    issue(0, 0);
    issue(1, 1);

    for (int c = 0; c < 8; ++c) {
        if (c + 2 < 8) { issue(c + 2, (c + 2) % 3); CP_WAIT2(); }
        else if (c + 1 < 8) { CP_WAIT1(); }
        else { CP_WAIT0(); }
        __syncthreads();

        const uint32_t ah = sbase + (c % 3) * STAGE_BYTES;
        const uint32_t bh = ah + 16384;

        #pragma unroll
        for (int ks = 0; ks < 4; ++ks) {
            uint32_t Ahf[4][4];
            #pragma unroll
            for (int mt = 0; mt < 4; ++mt) {
                const uint32_t off = sw128((uint32_t)((a_row + mt * 16) * 128 + ks * 32 + a_kb));
                LDSM4(Ahf[mt], ah + off);
            }
            uint32_t Bh[8];
            #pragma unroll
            for (int np = 0; np < 2; ++np) {
                const uint32_t off = sw128((uint32_t)((b_row + np * 16) * 128 + ks * 32 + b_kb));
                LDSM4(&Bh[np * 4], bh + off);
            }
            #pragma unroll
            for (int mt = 0; mt < 4; ++mt)
                #pragma unroll
                for (int nt = 0; nt < 4; ++nt)
                    MMA16816(acc[mt][nt], Ahf[mt], Bh[nt * 2], Bh[nt * 2 + 1]);
        }
        __syncthreads();
    }

    if (fuse_sm) {
        float* sm = (float*)dynsmem;   // 128 rows x stride 130
        #pragma unroll
        for (int mt = 0; mt < 4; ++mt) {
            const int r0 = warp_m * 64 + mt * 16 + (lid >> 2);
            #pragma unroll
            for (int nt = 0; nt < 4; ++nt) {
                const int cit = warp_n * 32 + nt * 8 + ((lid & 3) << 1);
                const float b0 = g_bp[wrow + cit], b1 = g_bp[wrow + cit + 1];
                sm[r0 * 130 + cit]           = acc[mt][nt][0] + b0;
                sm[r0 * 130 + cit + 1]       = acc[mt][nt][1] + b1;
                sm[(r0 + 8) * 130 + cit]     = acc[mt][nt][2] + b0;
                sm[(r0 + 8) * 130 + cit + 1] = acc[mt][nt][3] + b1;
            }
        }
        __syncthreads();
        __half* op = (__half*)outp;
        #pragma unroll
        for (int rr = 0; rr < 16; ++rr) {
            const int r = wid * 16 + rr;
            #pragma unroll
            for (int g = 0; g < 2; ++g) {
                float a = sm[r * 130 + g * 64 + lid];
                float b = sm[r * 130 + g * 64 + lid + 32];
                float m = fmaxf(a, b);
                #pragma unroll
                for (int o = 16; o > 0; o >>= 1)
                    m = fmaxf(m, __shfl_xor_sync(0xffffffffu, m, o));
                float ea = __expf(a - m), eb = __expf(b - m);
                float s = ea + eb;
                #pragma unroll
                for (int o = 16; o > 0; o >>= 1)
                    s += __shfl_xor_sync(0xffffffffu, s, o);
                const float inv = 1.0f / s;
                __half* p = op + (size_t)(bm + r) * EDIM + bn + g * 64;
                p[lid]      = __float2half_rn(ea * inv);
                p[lid + 32] = __float2half_rn(eb * inv);
            }
        }
    } else if (do_softmax) {
        __half* op = (__half*)outp;
        #pragma unroll
        for (int mt = 0; mt < 4; ++mt) {
            const int r0 = bm + warp_m * 64 + mt * 16 + (lid >> 2);
            #pragma unroll
            for (int nt = 0; nt < 4; ++nt) {
                const int cit = warp_n * 32 + nt * 8 + ((lid & 3) << 1);
                const float b0 = g_bp[wrow + cit], b1 = g_bp[wrow + cit + 1];
                const int col = bn + cit;
                *(__half2*)(op + (size_t)r0 * EDIM + col) =
                    __floats2half2_rn(acc[mt][nt][0] + b0, acc[mt][nt][1] + b1);
                *(__half2*)(op + (size_t)(r0 + 8) * EDIM + col) =
                    __floats2half2_rn(acc[mt][nt][2] + b0, acc[mt][nt][3] + b1);
            }
        }
    } else {
        float* op = (float*)outp;
        #pragma unroll
        for (int mt = 0; mt < 4; ++mt) {
            const int r0 = bm + warp_m * 64 + mt * 16 + (lid >> 2);
            #pragma unroll
            for (int nt = 0; nt < 4; ++nt) {
                const int cit = warp_n * 32 + nt * 8 + ((lid & 3) << 1);
                const float b0 = g_bp[wrow + cit], b1 = g_bp[wrow + cit + 1];
                const int col = bn + cit;
                *(float2*)(op + (size_t)r0 * EDIM + col) =
                    make_float2(acc[mt][nt][0] + b0, acc[mt][nt][1] + b1);
                *(float2*)(op + (size_t)(r0 + 8) * EDIM + col) =
                    make_float2(acc[mt][nt][2] + b0, acc[mt][nt][3] + b1);
            }
        }
    }
}

// ======== MMA stats with fused last-block reduction ========
// grid (NCHUNK, 32). per head, M = K^T V (64x64), ksum, vsum.
__global__ __launch_bounds__(256, 2)
void stats_mma_kernel()
{
    __shared__ __align__(1024) char smem[2 * 16384];
    __shared__ int s_last;
    const int n = blockIdx.y, b = n >> 3, h = n & 7;
    const int s0 = blockIdx.x * S_PER_CHUNK;
    const uint32_t sb = smem_u32(smem);
    const int tid = threadIdx.x, wid = tid >> 5, lid = tid & 31;
    const int warp_m = wid >> 2;
    const int warp_n = wid & 3;

    auto issue = [&](int t, int buf) {
        const uint32_t kb = sb + buf * 16384;
        const uint32_t vb = kb + 8192;
        #pragma unroll
        for (int it = 0; it < 2; ++it) {
            const int g = tid + it * 256;
            const int r = g >> 3, cg = g & 7;
            const int s = s0 + t * S_TILE + r;
            const size_t go = (size_t)(s * 4 + b) * EDIM + h * 64 + cg * 8;
            const uint32_t so = sw128((uint32_t)(r * 128 + cg * 16));
            CP16(kb + so, g_kh + go);
            CP16(vb + so, g_vh + go);
        }
        CP_COMMIT();
    };

    float acc[2][2][4] = {};
    float ksum = 0.f, vsum = 0.f;

    const int a_row = (lid & 7) + ((lid >> 4) & 1) * 8;
    const int a_by  = ((lid >> 3) & 1) * 16;
    const int b_row = (lid & 7) + ((lid >> 3) & 1) * 8;
    const int b_by  = ((lid >> 4) & 1) * 16;

    issue(0, 0);
    issue(1, 1);

    const int NT = S_PER_CHUNK / S_TILE;   // 8
    for (int t = 0; t < NT; ++t) {
        if (t < NT - 1) CP_WAIT1(); else CP_WAIT0();
        __syncthreads();
        const uint32_t kb = sb + (t & 1) * 16384;
        const uint32_t vb = kb + 8192;

        #pragma unroll
        for (int ks = 0; ks < 4; ++ks) {
            uint32_t Af[2][4];
            #pragma unroll
            for (int mt = 0; mt < 2; ++mt) {
                const uint32_t off = sw128((uint32_t)((ks * 16 + a_row) * 128
                                     + warp_m * 64 + mt * 32 + a_by));
                LDSM4T(Af[mt], kb + off);
            }
            uint32_t Bf[4];
            {
                const uint32_t off = sw128((uint32_t)((ks * 16 + b_row) * 128
                                     + warp_n * 32 + b_by));
                LDSM4T(Bf, vb + off);
            }
            #pragma unroll
            for (int mt = 0; mt < 2; ++mt)
                #pragma unroll
                for (int nt = 0; nt < 2; ++nt)
                    MMA16816(acc[mt][nt], Af[mt], Bf[nt * 2], Bf[nt * 2 + 1]);
        }

        if (tid < 128) {
            const uint32_t base = (tid < 64) ? kb : vb;
            const int d = tid & 63;
            float s = 0.f;
            #pragma unroll
            for (int r = 0; r < 64; ++r)
                s += __half2float(*(const __half*)(smem + (base - sb) + sw128((uint32_t)(r * 128 + d * 2))));
            if (tid < 64) ksum += s; else vsum += s;
        }
        __syncthreads();
        if (t + 2 < NT) issue(t + 2, t & 1);
    }

    float* pb = g_part + (size_t)(n * NCHUNK + blockIdx.x) * 4224;
    #pragma unroll
    for (int mt = 0; mt < 2; ++mt) {
        const int d1 = warp_m * 32 + mt * 16 + (lid >> 2);
        #pragma unroll
        for (int nt = 0; nt < 2; ++nt) {
            const int d2 = warp_n * 16 + nt * 8 + ((lid & 3) << 1);
            *(float2*)(pb + d1 * 64 + d2)       = make_float2(acc[mt][nt][0], acc[mt][nt][1]);
            *(float2*)(pb + (d1 + 8) * 64 + d2) = make_float2(acc[mt][nt][2], acc[mt][nt][3]);
        }
    }
    if (tid < 64)        pb[4096 + tid] = ksum;
    else if (tid < 128)  pb[4096 + tid] = vsum;

    // last-block-done reduction (deterministic order over chunk index)
    __syncthreads();
    __threadfence();
    if (tid == 0) {
        const unsigned v = atomicAdd(&g_cnt[n], 1u);
        s_last = (v == NCHUNK - 1);
    }
    __syncthreads();
    if (s_last) {
        for (int j = tid; j < 4224; j += 256) {
            float s = 0.f;
            #pragma unroll
            for (int c = 0; c < NCHUNK; ++c)
                s += g_part[(size_t)(n * NCHUNK + c) * 4224 + j];
            if (j < 4096)       g_Mh[n * 4096 + j] = __float2half_rn(s);
            else if (j < 4160)  g_ksum[n * 64 + (j - 4096)] = s;
            else                g_vsum[n * 64 + (j - 4160)] = s;
        }
        if (tid == 0) g_cnt[n] = 0;   // reset for next graph replay
    }
}

// ======== MMA combine: a = (62*Vsum + 2*q@M) / (62*2048 + 2*q.Ksum), fp16 ====
// grid (16, 32): 128 l-rows x 64 d2 per block.
__global__ __launch_bounds__(256, 2)
void combine_mma_kernel()
{
    __shared__ __align__(1024) char smem[16384 + 8192];  // q 16K, M 8K
    __shared__ float ksum_s[64], vsum_s[64], inv_s[128];
    const int n = blockIdx.y, b = n >> 3, h = n & 7;
    const int l0 = blockIdx.x << 7;
    const uint32_t qb = smem_u32(smem);
    const uint32_t mb = qb + 16384;
    const int tid = threadIdx.x, wid = tid >> 5, lid = tid & 31;
    const int warp_m = wid >> 1;   // 0..3 (32 l each)
    const int warp_n = wid & 1;    // 0..1 (32 d2 each)

    // load q tile (128 rows x 128B) and M tile (64 rows x 128B)
    #pragma unroll
    for (int it = 0; it < 4; ++it) {
        const int g = tid + it * 256;
        const int r = g >> 3, cg = g & 7;
        const size_t go = (size_t)((l0 + r) * 4 + b) * EDIM + h * 64 + cg * 8;
        CP16(qb + sw128((uint32_t)(r * 128 + cg * 16)), g_qh + go);
    }
    #pragma unroll
    for (int it = 0; it < 2; ++it) {
        const int g = tid + it * 256;
        const int r = g >> 3, cg = g & 7;
        CP16(mb + sw128((uint32_t)(r * 128 + cg * 16)), g_Mh + (size_t)n * 4096 + r * 64 + cg * 8);
    }
    CP_COMMIT();
    if (tid < 64) { ksum_s[tid] = g_ksum[n * 64 + tid]; vsum_s[tid] = g_vsum[n * 64 + tid]; }
    CP_WAIT0();
    __syncthreads();

    // per-row denominator
    if (tid < 128) {
        float s = 0.f;
        #pragma unroll
        for (int d = 0; d < 32; ++d) {
            const uint32_t off = sw128((uint32_t)(tid * 128 + d * 4));
            const float2 f = __half22float2(*(const __half2*)(smem + off));
            s += f.x * ksum_s[d * 2] + f.y * ksum_s[d * 2 + 1];
        }
        inv_s[tid] = 1.0f / (126976.0f + 2.0f * s);
    }
    __syncthreads();

    // q @ M via MMA
    float acc[2][4][4] = {};
    const int a_row = warp_m * 32 + (lid & 7) + ((lid >> 3) & 1) * 8;
    const int a_kb  = (lid >> 4) * 16;
    const int b_row = (lid & 7) + ((lid >> 3) & 1) * 8;
    const int b_by  = ((lid >> 4) & 1) * 16;

    #pragma unroll
    for (int ks = 0; ks < 4; ++ks) {
        uint32_t Af[2][4];
        #pragma unroll
        for (int mt = 0; mt < 2; ++mt)
            LDSM4(Af[mt], qb + sw128((uint32_t)((a_row + mt * 16) * 128 + ks * 32 + a_kb)));
        uint32_t Bf[2][4];
        #pragma unroll
        for (int hf = 0; hf < 2; ++hf)
            LDSM4T(Bf[hf], mb + sw128((uint32_t)((ks * 16 + b_row) * 128
                                 + warp_n * 64 + hf * 32 + b_by)));
        #pragma unroll
        for (int mt = 0; mt < 2; ++mt)
            #pragma unroll
            for (int nt = 0; nt < 4; ++nt)
                MMA16816(acc[mt][nt], Af[mt], Bf[nt >> 1][(nt & 1) * 2], Bf[nt >> 1][(nt & 1) * 2 + 1]);
    }

    #pragma unroll
    for (int mt = 0; mt < 2; ++mt) {
        const int l = warp_m * 32 + mt * 16 + (lid >> 2);
        const float i0 = inv_s[l], i1 = inv_s[l + 8];
        #pragma unroll
        for (int nt = 0; nt < 4; ++nt) {
            const int d2 = warp_n * 32 + nt * 8 + ((lid & 3) << 1);
            const float v0 = 62.f * vsum_s[d2], v1 = 62.f * vsum_s[d2 + 1];
            const size_t o0 = (size_t)((l0 + l) * 4 + b) * EDIM + h * 64 + d2;
            const size_t o1 = (size_t)((l0 + l + 8) * 4 + b) * EDIM + h * 64 + d2;
            *(uint32_t*)(g_ah + o0) = pack2h((v0 + 2.f * acc[mt][nt][0]) * i0,
                                             (v1 + 2.f * acc[mt][nt][1]) * i0);
            *(uint32_t*)(g_ah + o1) = pack2h((v0 + 2.f * acc[mt][nt][2]) * i1,
                                             (v1 + 2.f * acc[mt][nt][3]) * i1);
        }
    }
}

// ---------------- launch -----------------------------------------------------
extern "C" void kernel_launch(void* const* d_in, const int* in_sizes, int n_in,
                              void* d_out, int out_size)
{
    const float* query = (const float*)d_in[0];
    const float* Wq = (const float*)d_in[1];
    const float* bq = (const float*)d_in[2];
    const float* Wk = (const float*)d_in[3];
    const float* bk = (const float*)d_in[4];
    const float* Wv = (const float*)d_in[5];
    const float* bv = (const float*)d_in[6];
    const float* Wo = (const float*)d_in[7];
    const float* bo = (const float*)d_in[8];
    float* out = (float*)d_out;

    __half *qp, *kp, *vp, *xh, *ahp;
    cudaGetSymbolAddress((void**)&qp, g_qh);
    cudaGetSymbolAddress((void**)&kp, g_kh);
    cudaGetSymbolAddress((void**)&vp, g_vh);
    cudaGetSymbolAddress((void**)&xh, g_xh);
    cudaGetSymbolAddress((void**)&ahp, g_ah);

    cudaFuncSetAttribute(gemm_f16, cudaFuncAttributeMaxDynamicSharedMemorySize, SMEM_DYN);

    const int total = NQ4 + 4 * NW4 + EDIM;
    split_all_kernel<<<(total + 255) / 256, 256>>>(
        (const float4*)query, (const float4*)Wq, (const float4*)Wk,
        (const float4*)Wv, (const float4*)Wo, bq, bk, bv, bo);

    gemm_f16<<<dim3(12, 64), 256, SMEM_DYN>>>(xh, 0, 1, qp, kp, vp);
    stats_mma_kernel<<<dim3(NCHUNK, 32), 256>>>();
    combine_mma_kernel<<<dim3(16, 32), 256>>>();
    gemm_f16<<<dim3(4, 64), 256, SMEM_DYN>>>(ahp, 3 * EDIM, 0, out, out, out);
}

// round 11
// speedup vs baseline: 2.1402x; 1.0532x over previous
#include <cuda_runtime.h>
#include <cuda_fp16.h>
#include <cstdint>

#define EDIM   512
#define MROWS  8192
#define NCHUNK 4
#define S_PER_CHUNK 512
#define S_TILE 64

// ---------------- scratch (no allocation allowed) ----------------
__device__ __half g_qh[MROWS * EDIM];
__device__ __half g_kh[MROWS * EDIM];
__device__ __half g_vh[MROWS * EDIM];
__device__ float g_part[32 * NCHUNK * 4224];
__device__ __half g_Mh[32 * 4096];
__device__ float g_ksum[32 * 64];
__device__ float g_vsum[32 * 64];
__device__ unsigned g_cnt[32];             // zero-init; self-resetting
__device__ __half g_xh[MROWS * EDIM];      // query fp16
__device__ __half g_wh[4 * EDIM * EDIM];   // Wq|Wk|Wv|Wo fp16
__device__ __half g_ah[MROWS * EDIM];      // attention-out fp16
__device__ float g_bp[4 * EDIM];

// =================== helpers ===================
__device__ __forceinline__ uint32_t smem_u32(const void* p) {
    uint32_t a;
    asm("{ .reg .u64 t; cvta.to.shared.u64 t, %1; cvt.u32.u64 %0, t; }" : "=r"(a) : "l"(p));
    return a;
}
__device__ __forceinline__ uint32_t sw128(uint32_t off) { return off ^ ((off >> 3) & 0x70); }

__device__ __forceinline__ uint32_t pack2h(float a, float b) {
    __half2 h = __floats2half2_rn(a, b);
    return *(uint32_t*)&h;
}
#define LDSM4(r, addr) \
    asm volatile("ldmatrix.sync.aligned.m8n8.x4.shared.b16 {%0,%1,%2,%3}, [%4];" \
        : "=r"((r)[0]), "=r"((r)[1]), "=r"((r)[2]), "=r"((r)[3]) : "r"(addr))
#define LDSM4T(r, addr) \
    asm volatile("ldmatrix.sync.aligned.m8n8.x4.trans.shared.b16 {%0,%1,%2,%3}, [%4];" \
        : "=r"((r)[0]), "=r"((r)[1]), "=r"((r)[2]), "=r"((r)[3]) : "r"(addr))
#define MMA16816(d, a, b0, b1) \
    asm volatile("mma.sync.aligned.m16n8k16.row.col.f32.f16.f16.f32 " \
        "{%0,%1,%2,%3},{%4,%5,%6,%7},{%8,%9},{%0,%1,%2,%3};" \
        : "+f"((d)[0]), "+f"((d)[1]), "+f"((d)[2]), "+f"((d)[3]) \
        : "r"((a)[0]), "r"((a)[1]), "r"((a)[2]), "r"((a)[3]), "r"(b0), "r"(b1))
#define CP16(saddr, gptr) \
    asm volatile("cp.async.cg.shared.global [%0], [%1], 16;" :: "r"(saddr), "l"(gptr))
#define CP_COMMIT() asm volatile("cp.async.commit_group;" ::: "memory")
#define CP_WAIT2()  asm volatile("cp.async.wait_group 2;" ::: "memory")
#define CP_WAIT1()  asm volatile("cp.async.wait_group 1;" ::: "memory")
#define CP_WAIT0()  asm volatile("cp.async.wait_group 0;" ::: "memory")

// ------------- one fused fp32 -> fp16 conversion for ALL operands -------------
#define NQ4  (MROWS * EDIM / 4)
#define NW4  (EDIM * EDIM / 4)
__global__ void split_all_kernel(const float4* __restrict__ q,
                                 const float4* __restrict__ wq, const float4* __restrict__ wk,
                                 const float4* __restrict__ wv, const float4* __restrict__ wo,
                                 const float* __restrict__ bq, const float* __restrict__ bk,
                                 const float* __restrict__ bv, const float* __restrict__ bo)
{
    const int i = blockIdx.x * blockDim.x + threadIdx.x;
    const int total = NQ4 + 4 * NW4;
    if (i < NQ4) {
        const float4 x = q[i];
        ((uint2*)g_xh)[i] = make_uint2(pack2h(x.x, x.y), pack2h(x.z, x.w));
    } else if (i < total) {
        const int j = i - NQ4;
        const int w = j / NW4, off = j % NW4;
        const float4* src = (w == 0) ? wq : (w == 1) ? wk : (w == 2) ? wv : wo;
        const float4 x = src[off];
        ((uint2*)g_wh)[j] = make_uint2(pack2h(x.x, x.y), pack2h(x.z, x.w));
    } else if (i < total + EDIM) {
        const int t = i - total;
        g_bp[t] = bq[t];
        g_bp[EDIM + t] = bk[t];
        g_bp[2 * EDIM + t] = bv[t];
        g_bp[3 * EDIM + t] = bo[t];
    }
}

// ======== fp16 single-pass warp-MMA GEMM, 3-stage cp.async pipeline ========
#define STAGE_BYTES 32768
#define SMEM_DYN (3 * STAGE_BYTES)

extern __shared__ __align__(1024) char dynsmem[];

__global__ __launch_bounds__(256, 2)
void gemm_f16(const __half* __restrict__ Ah,
              int wbase, int do_softmax,
              void* __restrict__ out0, void* __restrict__ out1, void* __restrict__ out2)
{
    const uint32_t sbase = smem_u32(dynsmem);
    const int tid = threadIdx.x;
    const int wid = tid >> 5, lid = tid & 31;
    const int warp_m = wid >> 2;
    const int warp_n = wid & 3;
    const int nb = blockIdx.x;
    const int bm = blockIdx.y << 7;
    const int bn = (nb & 3) << 7;
    const int sel = nb >> 2;
    void* outp = (sel == 0) ? out0 : ((sel == 1) ? out1 : out2);
    const int wrow = wbase + nb * 128;
    const int fuse_sm = do_softmax && (sel < 2);

    int cp_r[4], cp_cg[4];
    uint32_t cp_soff[4];
    #pragma unroll
    for (int it = 0; it < 4; ++it) {
        const int g = tid + it * 256;
        cp_r[it] = g >> 3;
        cp_cg[it] = g & 7;
        cp_soff[it] = sw128((uint32_t)(cp_r[it] * 128 + cp_cg[it] * 16));
    }

    float acc[4][4][4] = {};
    const int a_row = warp_m * 64 + (lid & 7) + ((lid >> 3) & 1) * 8;
    const int a_kb  = (lid >> 4) * 16;
    const int b_row = warp_n * 32 + (lid & 7) + (lid >> 4) * 8;
    const int b_kb  = ((lid >> 3) & 1) * 16;

    auto issue = [&](int c, int buf) {
        const uint32_t ah = sbase + buf * STAGE_BYTES;
        const uint32_t bh = ah + 16384;
        const int kof = c * 64;
        #pragma unroll
        for (int it = 0; it < 4; ++it) {
            const size_t aoff = (size_t)(bm + cp_r[it]) * EDIM + kof + cp_cg[it] * 8;
            const size_t boff = (size_t)(wrow + cp_r[it]) * EDIM + kof + cp_cg[it] * 8;
            CP16(ah + cp_soff[it], Ah + aoff);
            CP16(bh + cp_soff[it], g_wh + boff);
        }
        CP_COMMIT();
    };

    issue(0, 0);
    issue(1, 1);

    for (int c = 0; c < 8; ++c) {
        if (c + 2 < 8) { issue(c + 2, (c + 2) % 3); CP_WAIT2(); }
        else if (c + 1 < 8) { CP_WAIT1(); }
        else { CP_WAIT0(); }
        __syncthreads();

        const uint32_t ah = sbase + (c % 3) * STAGE_BYTES;
        const uint32_t bh = ah + 16384;

        #pragma unroll
        for (int ks = 0; ks < 4; ++ks) {
            uint32_t Ahf[4][4];
            #pragma unroll
            for (int mt = 0; mt < 4; ++mt) {
                const uint32_t off = sw128((uint32_t)((a_row + mt * 16) * 128 + ks * 32 + a_kb));
                LDSM4(Ahf[mt], ah + off);
            }
            uint32_t Bh[8];
            #pragma unroll
            for (int np = 0; np < 2; ++np) {
                const uint32_t off = sw128((uint32_t)((b_row + np * 16) * 128 + ks * 32 + b_kb));
                LDSM4(&Bh[np * 4], bh + off);
            }
            #pragma unroll
            for (int mt = 0; mt < 4; ++mt)
                #pragma unroll
                for (int nt = 0; nt < 4; ++nt)
                    MMA16816(acc[mt][nt], Ahf[mt], Bh[nt * 2], Bh[nt * 2 + 1]);
        }
        __syncthreads();
    }

    if (fuse_sm) {
        float* sm = (float*)dynsmem;   // 128 rows x stride 130
        #pragma unroll
        for (int mt = 0; mt < 4; ++mt) {
            const int r0 = warp_m * 64 + mt * 16 + (lid >> 2);
            #pragma unroll
            for (int nt = 0; nt < 4; ++nt) {
                const int cit = warp_n * 32 + nt * 8 + ((lid & 3) << 1);
                const float b0 = g_bp[wrow + cit], b1 = g_bp[wrow + cit + 1];
                sm[r0 * 130 + cit]           = acc[mt][nt][0] + b0;
                sm[r0 * 130 + cit + 1]       = acc[mt][nt][1] + b1;
                sm[(r0 + 8) * 130 + cit]     = acc[mt][nt][2] + b0;
                sm[(r0 + 8) * 130 + cit + 1] = acc[mt][nt][3] + b1;
            }
        }
        __syncthreads();
        __half* op = (__half*)outp;
        #pragma unroll
        for (int rr = 0; rr < 16; ++rr) {
            const int r = wid * 16 + rr;
            #pragma unroll
            for (int g = 0; g < 2; ++g) {
                float a = sm[r * 130 + g * 64 + lid];
                float b = sm[r * 130 + g * 64 + lid + 32];
                float m = fmaxf(a, b);
                #pragma unroll
                for (int o = 16; o > 0; o >>= 1)
                    m = fmaxf(m, __shfl_xor_sync(0xffffffffu, m, o));
                float ea = __expf(a - m), eb = __expf(b - m);
                float s = ea + eb;
                #pragma unroll
                for (int o = 16; o > 0; o >>= 1)
                    s += __shfl_xor_sync(0xffffffffu, s, o);
                const float inv = 1.0f / s;
                __half* p = op + (size_t)(bm + r) * EDIM + bn + g * 64;
                p[lid]      = __float2half_rn(ea * inv);
                p[lid + 32] = __float2half_rn(eb * inv);
            }
        }
    } else if (do_softmax) {
        __half* op = (__half*)outp;
        #pragma unroll
        for (int mt = 0; mt < 4; ++mt) {
            const int r0 = bm + warp_m * 64 + mt * 16 + (lid >> 2);
            #pragma unroll
            for (int nt = 0; nt < 4; ++nt) {
                const int cit = warp_n * 32 + nt * 8 + ((lid & 3) << 1);
                const float b0 = g_bp[wrow + cit], b1 = g_bp[wrow + cit + 1];
                const int col = bn + cit;
                *(__half2*)(op + (size_t)r0 * EDIM + col) =
                    __floats2half2_rn(acc[mt][nt][0] + b0, acc[mt][nt][1] + b1);
                *(__half2*)(op + (size_t)(r0 + 8) * EDIM + col) =
                    __floats2half2_rn(acc[mt][nt][2] + b0, acc[mt][nt][3] + b1);
            }
        }
    } else {
        float* op = (float*)outp;
        #pragma unroll
        for (int mt = 0; mt < 4; ++mt) {
            const int r0 = bm + warp_m * 64 + mt * 16 + (lid >> 2);
            #pragma unroll
            for (int nt = 0; nt < 4; ++nt) {
                const int cit = warp_n * 32 + nt * 8 + ((lid & 3) << 1);
                const float b0 = g_bp[wrow + cit], b1 = g_bp[wrow + cit + 1];
                const int col = bn + cit;
                *(float2*)(op + (size_t)r0 * EDIM + col) =
                    make_float2(acc[mt][nt][0] + b0, acc[mt][nt][1] + b1);
                *(float2*)(op + (size_t)(r0 + 8) * EDIM + col) =
                    make_float2(acc[mt][nt][2] + b0, acc[mt][nt][3] + b1);
            }
        }
    }
}

// ======== MMA stats with fused last-block reduction ========
__global__ __launch_bounds__(256, 2)
void stats_mma_kernel()
{
    __shared__ __align__(1024) char smem[2 * 16384];
    __shared__ int s_last;
    const int n = blockIdx.y, b = n >> 3, h = n & 7;
    const int s0 = blockIdx.x * S_PER_CHUNK;
    const uint32_t sb = smem_u32(smem);
    const int tid = threadIdx.x, wid = tid >> 5, lid = tid & 31;
    const int warp_m = wid >> 2;
    const int warp_n = wid & 3;

    auto issue = [&](int t, int buf) {
        const uint32_t kb = sb + buf * 16384;
        const uint32_t vb = kb + 8192;
        #pragma unroll
        for (int it = 0; it < 2; ++it) {
            const int g = tid + it * 256;
            const int r = g >> 3, cg = g & 7;
            const int s = s0 + t * S_TILE + r;
            const size_t go = (size_t)(s * 4 + b) * EDIM + h * 64 + cg * 8;
            const uint32_t so = sw128((uint32_t)(r * 128 + cg * 16));
            CP16(kb + so, g_kh + go);
            CP16(vb + so, g_vh + go);
        }
        CP_COMMIT();
    };

    float acc[2][2][4] = {};
    float ksum = 0.f, vsum = 0.f;

    const int a_row = (lid & 7) + ((lid >> 4) & 1) * 8;
    const int a_by  = ((lid >> 3) & 1) * 16;
    const int b_row = (lid & 7) + ((lid >> 3) & 1) * 8;
    const int b_by  = ((lid >> 4) & 1) * 16;

    issue(0, 0);
    issue(1, 1);

    const int NT = S_PER_CHUNK / S_TILE;   // 8
    for (int t = 0; t < NT; ++t) {
        if (t < NT - 1) CP_WAIT1(); else CP_WAIT0();
        __syncthreads();
        const uint32_t kb = sb + (t & 1) * 16384;
        const uint32_t vb = kb + 8192;

        #pragma unroll
        for (int ks = 0; ks < 4; ++ks) {
            uint32_t Af[2][4];
            #pragma unroll
            for (int mt = 0; mt < 2; ++mt) {
                const uint32_t off = sw128((uint32_t)((ks * 16 + a_row) * 128
                                     + warp_m * 64 + mt * 32 + a_by));
                LDSM4T(Af[mt], kb + off);
            }
            uint32_t Bf[4];
            {
                const uint32_t off = sw128((uint32_t)((ks * 16 + b_row) * 128
                                     + warp_n * 32 + b_by));
                LDSM4T(Bf, vb + off);
            }
            #pragma unroll
            for (int mt = 0; mt < 2; ++mt)
                #pragma unroll
                for (int nt = 0; nt < 2; ++nt)
                    MMA16816(acc[mt][nt], Af[mt], Bf[nt * 2], Bf[nt * 2 + 1]);
        }

        if (tid < 128) {
            const uint32_t base = (tid < 64) ? kb : vb;
            const int d = tid & 63;
            float s = 0.f;
            #pragma unroll
            for (int r = 0; r < 64; ++r)
                s += __half2float(*(const __half*)(smem + (base - sb) + sw128((uint32_t)(r * 128 + d * 2))));
            if (tid < 64) ksum += s; else vsum += s;
        }
        __syncthreads();
        if (t + 2 < NT) issue(t + 2, t & 1);
    }

    float* pb = g_part + (size_t)(n * NCHUNK + blockIdx.x) * 4224;
    #pragma unroll
    for (int mt = 0; mt < 2; ++mt) {
        const int d1 = warp_m * 32 + mt * 16 + (lid >> 2);
        #pragma unroll
        for (int nt = 0; nt < 2; ++nt) {
            const int d2 = warp_n * 16 + nt * 8 + ((lid & 3) << 1);
            *(float2*)(pb + d1 * 64 + d2)       = make_float2(acc[mt][nt][0], acc[mt][nt][1]);
            *(float2*)(pb + (d1 + 8) * 64 + d2) = make_float2(acc[mt][nt][2], acc[mt][nt][3]);
        }
    }
    if (tid < 64)        pb[4096 + tid] = ksum;
    else if (tid < 128)  pb[4096 + tid] = vsum;

    __syncthreads();
    __threadfence();
    if (tid == 0) {
        const unsigned v = atomicAdd(&g_cnt[n], 1u);
        s_last = (v == NCHUNK - 1);
    }
    __syncthreads();
    if (s_last) {
        for (int j = tid; j < 4224; j += 256) {
            float s = 0.f;
            #pragma unroll
            for (int c = 0; c < NCHUNK; ++c)
                s += g_part[(size_t)(n * NCHUNK + c) * 4224 + j];
            if (j < 4096)       g_Mh[n * 4096 + j] = __float2half_rn(s);
            else if (j < 4160)  g_ksum[n * 64 + (j - 4096)] = s;
            else                g_vsum[n * 64 + (j - 4160)] = s;
        }
        if (tid == 0) g_cnt[n] = 0;
    }
}

// ======== MMA combine: a = (62*Vsum + 2*q@M) / (62*2048 + 2*q.Ksum), fp16 ====
// grid (32, 32): 64 l-rows x 64 d2 per block. Latency-optimized.
__global__ __launch_bounds__(256)
void combine_mma_kernel()
{
    __shared__ __align__(1024) char smem[8192 + 8192];  // q 8K, M 8K
    __shared__ float ksum_s[64], vsum_s[64], inv_s[64];
    const int n = blockIdx.y, b = n >> 3, h = n & 7;
    const int l0 = blockIdx.x << 6;
    const uint32_t qb = smem_u32(smem);
    const uint32_t mb = qb + 8192;
    const int tid = threadIdx.x, wid = tid >> 5, lid = tid & 31;
    const int warp_m = wid >> 1;   // 0..3 (16 l each)
    const int warp_n = wid & 1;    // 0..1 (32 d2 each)

    // q tile (64 rows x 128B) + M tile (64 rows x 128B), one commit
    #pragma unroll
    for (int it = 0; it < 2; ++it) {
        const int g = tid + it * 256;
        const int r = g >> 3, cg = g & 7;
        const size_t go = (size_t)((l0 + r) * 4 + b) * EDIM + h * 64 + cg * 8;
        const uint32_t so = sw128((uint32_t)(r * 128 + cg * 16));
        CP16(qb + so, g_qh + go);
        CP16(mb + so, g_Mh + (size_t)n * 4096 + r * 64 + cg * 8);
    }
    CP_COMMIT();
    // overlap: ksum/vsum LDG while cp.async is in flight
    if (tid < 64) { ksum_s[tid] = g_ksum[n * 64 + tid]; vsum_s[tid] = g_vsum[n * 64 + tid]; }
    CP_WAIT0();
    __syncthreads();

    // denominator: 4 threads per row, 16 halves each, shfl-combine
    {
        const int row = tid >> 2;          // 0..63
        const int qr  = tid & 3;           // quarter
        float s = 0.f;
        #pragma unroll
        for (int p = 0; p < 8; ++p) {
            const int d = qr * 16 + p * 2;
            const uint32_t off = sw128((uint32_t)(row * 128 + d * 2));
            const float2 f = __half22float2(*(const __half2*)(smem + off));
            s += f.x * ksum_s[d] + f.y * ksum_s[d + 1];
        }
        s += __shfl_xor_sync(0xffffffffu, s, 1);
        s += __shfl_xor_sync(0xffffffffu, s, 2);
        if (qr == 0) inv_s[row] = 1.0f / (126976.0f + 2.0f * s);
    }
    __syncthreads();

    // q @ M via MMA: 64x64x64; warp tile 16 l x 32 d2
    float acc[4][4] = {};
    const int a_row = warp_m * 16 + (lid & 7) + ((lid >> 3) & 1) * 8;
    const int a_kb  = (lid >> 4) * 16;
    const int b_row = (lid & 7) + ((lid >> 3) & 1) * 8;
    const int b_by  = ((lid >> 4) & 1) * 16;

    #pragma unroll
    for (int ks = 0; ks < 4; ++ks) {
        uint32_t Af[4];
        LDSM4(Af, qb + sw128((uint32_t)(a_row * 128 + ks * 32 + a_kb)));
        uint32_t Bf[2][4];
        #pragma unroll
        for (int hf = 0; hf < 2; ++hf)
            LDSM4T(Bf[hf], mb + sw128((uint32_t)((ks * 16 + b_row) * 128
                                 + warp_n * 64 + hf * 32 + b_by)));
        #pragma unroll
        for (int nt = 0; nt < 4; ++nt)
            MMA16816(acc[nt], Af, Bf[nt >> 1][(nt & 1) * 2], Bf[nt >> 1][(nt & 1) * 2 + 1]);
    }

    {
        const int l = warp_m * 16 + (lid >> 2);
        const float i0 = inv_s[l], i1 = inv_s[l + 8];
        #pragma unroll
        for (int nt = 0; nt < 4; ++nt) {
            const int d2 = warp_n * 32 + nt * 8 + ((lid & 3) << 1);
            const float v0 = 62.f * vsum_s[d2], v1 = 62.f * vsum_s[d2 + 1];
            const size_t o0 = (size_t)((l0 + l) * 4 + b) * EDIM + h * 64 + d2;
            const size_t o1 = (size_t)((l0 + l + 8) * 4 + b) * EDIM + h * 64 + d2;
            *(uint32_t*)(g_ah + o0) = pack2h((v0 + 2.f * acc[nt][0]) * i0,
                                             (v1 + 2.f * acc[nt][1]) * i0);
            *(uint32_t*)(g_ah + o1) = pack2h((v0 + 2.f * acc[nt][2]) * i1,
                                             (v1 + 2.f * acc[nt][3]) * i1);
        }
    }
}

// ---------------- launch -----------------------------------------------------
extern "C" void kernel_launch(void* const* d_in, const int* in_sizes, int n_in,
                              void* d_out, int out_size)
{
    const float* query = (const float*)d_in[0];
    const float* Wq = (const float*)d_in[1];
    const float* bq = (const float*)d_in[2];
    const float* Wk = (const float*)d_in[3];
    const float* bk = (const float*)d_in[4];
    const float* Wv = (const float*)d_in[5];
    const float* bv = (const float*)d_in[6];
    const float* Wo = (const float*)d_in[7];
    const float* bo = (const float*)d_in[8];
    float* out = (float*)d_out;

    __half *qp, *kp, *vp, *xh, *ahp;
    cudaGetSymbolAddress((void**)&qp, g_qh);
    cudaGetSymbolAddress((void**)&kp, g_kh);
    cudaGetSymbolAddress((void**)&vp, g_vh);
    cudaGetSymbolAddress((void**)&xh, g_xh);
    cudaGetSymbolAddress((void**)&ahp, g_ah);

    cudaFuncSetAttribute(gemm_f16, cudaFuncAttributeMaxDynamicSharedMemorySize, SMEM_DYN);

    const int total = NQ4 + 4 * NW4 + EDIM;
    split_all_kernel<<<(total + 255) / 256, 256>>>(
        (const float4*)query, (const float4*)Wq, (const float4*)Wk,
        (const float4*)Wv, (const float4*)Wo, bq, bk, bv, bo);

    gemm_f16<<<dim3(12, 64), 256, SMEM_DYN>>>(xh, 0, 1, qp, kp, vp);
    stats_mma_kernel<<<dim3(NCHUNK, 32), 256>>>();
    combine_mma_kernel<<<dim3(32, 32), 256>>>();
    gemm_f16<<<dim3(4, 64), 256, SMEM_DYN>>>(ahp, 3 * EDIM, 0, out, out, out);
}